// round 2
// baseline (speedup 1.0000x reference)
#include <cuda_runtime.h>
#include <math.h>

// Problem constants
#define Bv   4
#define Sv   4096
#define Dv   1024
#define Hv   16
#define HDv  64
#define LKv  256
#define Mrows (Bv*Sv)        // 16384

// ---------------- scratch (static device globals; no allocation allowed) ----
__device__ float g_Q [(long long)Mrows * Dv];   // 64 MB
__device__ float g_K [(long long)Mrows * Dv];   // 64 MB (already masked)
__device__ float g_V [(long long)Mrows * Dv];   // 64 MB (already masked)
__device__ float g_Xo[(long long)Mrows * Dv];   // 64 MB
__device__ float g_Kp[(long long)Bv * Hv * LKv * HDv];  // 16 MB
__device__ float g_Vp[(long long)Bv * Hv * LKv * HDv];  // 16 MB

// ============================================================================
// SGEMM: out[M,N] = A[M,K] @ W[K,N] + bias[N], optionally scaled per-row by
// rowscale[m] (applied AFTER bias, matching reference (X@Wk + bk) * mask).
// BM=128, BN=128, BK=16, 256 threads, each thread computes 8x8.
// ============================================================================
__global__ __launch_bounds__(256) void sgemm_bias_kernel(
    const float* __restrict__ A, const float* __restrict__ W,
    const float* __restrict__ bias, const float* __restrict__ rowscale,
    float* __restrict__ out, int M, int N, int K)
{
    __shared__ float As[16][132];   // [k][m], padded stride to reduce conflicts
    __shared__ float Bs[16][128];   // [k][n]

    const int m0 = blockIdx.y * 128;
    const int n0 = blockIdx.x * 128;
    const int t  = threadIdx.x;
    const int tx = t & 15;          // n-tile  (tx*8)
    const int ty = t >> 4;          // m-tile  (ty*8)

    // load mappings
    const int arow = t >> 2;            // 0..63
    const int acol = (t & 3) * 4;       // 0,4,8,12
    const int brow = t >> 5;            // 0..7
    const int bcol = (t & 31) * 4;      // 0..124

    float acc[8][8];
    #pragma unroll
    for (int i = 0; i < 8; i++)
        #pragma unroll
        for (int j = 0; j < 8; j++) acc[i][j] = 0.0f;

    for (int k0 = 0; k0 < K; k0 += 16) {
        // A tile: 128 rows x 16 cols, stored transposed into As[k][m]
        #pragma unroll
        for (int i = 0; i < 2; i++) {
            int r = arow + i * 64;
            float4 v = *(const float4*)&A[(size_t)(m0 + r) * K + k0 + acol];
            As[acol + 0][r] = v.x;
            As[acol + 1][r] = v.y;
            As[acol + 2][r] = v.z;
            As[acol + 3][r] = v.w;
        }
        // B tile: 16 rows x 128 cols
        #pragma unroll
        for (int i = 0; i < 2; i++) {
            int r = brow + i * 8;
            float4 v = *(const float4*)&W[(size_t)(k0 + r) * N + n0 + bcol];
            *(float4*)&Bs[r][bcol] = v;
        }
        __syncthreads();

        #pragma unroll
        for (int kk = 0; kk < 16; kk++) {
            float a[8], b[8];
            float4 a0 = *(const float4*)&As[kk][ty * 8];
            float4 a1 = *(const float4*)&As[kk][ty * 8 + 4];
            float4 b0 = *(const float4*)&Bs[kk][tx * 8];
            float4 b1 = *(const float4*)&Bs[kk][tx * 8 + 4];
            a[0]=a0.x; a[1]=a0.y; a[2]=a0.z; a[3]=a0.w;
            a[4]=a1.x; a[5]=a1.y; a[6]=a1.z; a[7]=a1.w;
            b[0]=b0.x; b[1]=b0.y; b[2]=b0.z; b[3]=b0.w;
            b[4]=b1.x; b[5]=b1.y; b[6]=b1.z; b[7]=b1.w;
            #pragma unroll
            for (int i = 0; i < 8; i++)
                #pragma unroll
                for (int j = 0; j < 8; j++)
                    acc[i][j] = fmaf(a[i], b[j], acc[i][j]);
        }
        __syncthreads();
    }

    // epilogue: bias (+ optional per-row mask scale)
    #pragma unroll
    for (int i = 0; i < 8; i++) {
        int m = m0 + ty * 8 + i;
        float ms = rowscale ? rowscale[m] : 1.0f;
        #pragma unroll
        for (int j = 0; j < 8; j += 4) {
            int n = n0 + tx * 8 + j;
            float4 v;
            v.x = (acc[i][j + 0] + bias[n + 0]) * ms;
            v.y = (acc[i][j + 1] + bias[n + 1]) * ms;
            v.z = (acc[i][j + 2] + bias[n + 2]) * ms;
            v.w = (acc[i][j + 3] + bias[n + 3]) * ms;
            *(float4*)&out[(size_t)m * N + n] = v;
        }
    }
}

// ============================================================================
// Projection: Kp[b,h,k,d] = sum_s E[h,k,s] * K[b,s,h*64+d]   (K pre-masked)
// Per (b,h): M=256(k), N=64(d), inner=4096(s). Block tile 64x64, BK=16,
// 256 threads, 4x4 per thread. grid = (LK/64=4, B*H=64, 2[K|V]).
// ============================================================================
__global__ __launch_bounds__(256) void proj_kernel(
    const float* __restrict__ E)
{
    __shared__ float Es[16][65];    // [s][k] transposed, padded
    __shared__ float Ks[16][64];    // [s][d]

    const int k0b = blockIdx.x * 64;
    const int bh  = blockIdx.y;
    const int b   = bh >> 4;
    const int h   = bh & 15;
    const int z   = blockIdx.z;

    const float* src = z == 0 ? g_K : g_V;
    float*       dst = z == 0 ? g_Kp : g_Vp;

    const int t  = threadIdx.x;
    const int tx = t & 15;          // d  (tx*4)
    const int ty = t >> 4;          // k  (ty*4)

    const int erow = t >> 2;            // 0..63 (k within tile)
    const int ecol = (t & 3) * 4;       // 0..12 (s within tile)
    const int krow = t >> 4;            // 0..15 (s within tile)
    const int kcol = (t & 15) * 4;      // 0..60 (d)

    const float* Eb = E + ((size_t)h * LKv + k0b) * Sv;
    const float* Kb = src + (size_t)b * Sv * Dv + h * HDv;

    float acc[4][4];
    #pragma unroll
    for (int i = 0; i < 4; i++)
        #pragma unroll
        for (int j = 0; j < 4; j++) acc[i][j] = 0.0f;

    for (int s0 = 0; s0 < Sv; s0 += 16) {
        float4 ev = *(const float4*)&Eb[(size_t)erow * Sv + s0 + ecol];
        Es[ecol + 0][erow] = ev.x;
        Es[ecol + 1][erow] = ev.y;
        Es[ecol + 2][erow] = ev.z;
        Es[ecol + 3][erow] = ev.w;
        float4 kv = *(const float4*)&Kb[(size_t)(s0 + krow) * Dv + kcol];
        *(float4*)&Ks[krow][kcol] = kv;
        __syncthreads();

        #pragma unroll
        for (int kk = 0; kk < 16; kk++) {
            float a[4];
            float4 bv4 = *(const float4*)&Ks[kk][tx * 4];
            a[0] = Es[kk][ty * 4 + 0];
            a[1] = Es[kk][ty * 4 + 1];
            a[2] = Es[kk][ty * 4 + 2];
            a[3] = Es[kk][ty * 4 + 3];
            float bb[4] = {bv4.x, bv4.y, bv4.z, bv4.w};
            #pragma unroll
            for (int i = 0; i < 4; i++)
                #pragma unroll
                for (int j = 0; j < 4; j++)
                    acc[i][j] = fmaf(a[i], bb[j], acc[i][j]);
        }
        __syncthreads();
    }

    float* ob = dst + (size_t)bh * LKv * HDv;
    #pragma unroll
    for (int i = 0; i < 4; i++) {
        int k = k0b + ty * 4 + i;
        float4 v = {acc[i][0], acc[i][1], acc[i][2], acc[i][3]};
        *(float4*)&ob[(size_t)k * HDv + tx * 4] = v;
    }
}

// ============================================================================
// Fused attention: per (b,h), stage Kp^T and Vp in smem, then per query row:
// dot(q, Kp) / 8 -> softmax over LK=256 -> weighted sum of Vp.
// grid = (S/64, B*H); 256 threads (8 warps); each warp handles 8 rows.
// ============================================================================
#define ATTN_SMEM_FLOATS (64*257 + 256*64 + 8*256 + 8*64)

__global__ __launch_bounds__(256) void attn_kernel()
{
    extern __shared__ float sm[];
    float* Kpt   = sm;                       // [64][257]  Kp transposed [d][k]
    float* Vps   = Kpt + 64 * 257;           // [256][64]  Vp [k][d]
    float* attnb = Vps + 256 * 64;           // [8][256]   per-warp attn row
    float* qs    = attnb + 8 * 256;          // [8][64]    per-warp q row

    const int bh   = blockIdx.y;
    const int b    = bh >> 4;
    const int h    = bh & 15;
    const int s0   = blockIdx.x * 64;
    const int t    = threadIdx.x;
    const int lane = t & 31;
    const int w    = t >> 5;

    const float* Kp = g_Kp + (size_t)bh * LKv * HDv;
    const float* Vp = g_Vp + (size_t)bh * LKv * HDv;

    // cooperative staging (coalesced global reads; padded transposed store)
    #pragma unroll
    for (int i = 0; i < 64; i++) {
        int e = t + i * 256;
        int k = e >> 6, d = e & 63;
        Kpt[d * 257 + k] = Kp[e];
        Vps[e]           = Vp[e];
    }
    __syncthreads();

    const float* Qh = g_Q + (size_t)b * Sv * Dv + h * HDv;
    float* Oh       = g_Xo + (size_t)b * Sv * Dv + h * HDv;

    for (int r = 0; r < 8; r++) {
        const int s = s0 + w * 8 + r;
        const float* q = Qh + (size_t)s * Dv;
        qs[w * 64 + lane]      = q[lane];
        qs[w * 64 + lane + 32] = q[lane + 32];
        __syncwarp();

        // dot: each lane owns k = jj*32 + lane (8 values)
        float acc[8] = {0, 0, 0, 0, 0, 0, 0, 0};
        #pragma unroll 8
        for (int d = 0; d < 64; d++) {
            float qd = qs[w * 64 + d];
            #pragma unroll
            for (int jj = 0; jj < 8; jj++)
                acc[jj] = fmaf(qd, Kpt[d * 257 + jj * 32 + lane], acc[jj]);
        }

        // softmax over LK=256 (warp-wide)
        float mx = -1e30f;
        #pragma unroll
        for (int jj = 0; jj < 8; jj++) { acc[jj] *= 0.125f; mx = fmaxf(mx, acc[jj]); }
        #pragma unroll
        for (int o = 16; o > 0; o >>= 1)
            mx = fmaxf(mx, __shfl_xor_sync(0xffffffffu, mx, o));
        float sum = 0.0f;
        #pragma unroll
        for (int jj = 0; jj < 8; jj++) { acc[jj] = __expf(acc[jj] - mx); sum += acc[jj]; }
        #pragma unroll
        for (int o = 16; o > 0; o >>= 1)
            sum += __shfl_xor_sync(0xffffffffu, sum, o);
        float inv = 1.0f / sum;
        #pragma unroll
        for (int jj = 0; jj < 8; jj++)
            attnb[w * 256 + jj * 32 + lane] = acc[jj] * inv;
        __syncwarp();

        // out[d] = sum_k attn[k] * Vp[k][d]; lane owns d = lane, lane+32
        float o0 = 0.0f, o1 = 0.0f;
        #pragma unroll 4
        for (int k = 0; k < 256; k++) {
            float a = attnb[w * 256 + k];
            o0 = fmaf(a, Vps[k * 64 + lane],      o0);
            o1 = fmaf(a, Vps[k * 64 + lane + 32], o1);
        }
        float* op = Oh + (size_t)s * Dv;
        op[lane]      = o0;
        op[lane + 32] = o1;
        __syncwarp();
    }
}

// ============================================================================
extern "C" void kernel_launch(void* const* d_in, const int* in_sizes, int n_in,
                              void* d_out, int out_size)
{
    const float* X    = (const float*)d_in[0];
    const float* mask = (const float*)d_in[1];
    const float* Wq   = (const float*)d_in[2];
    const float* bq   = (const float*)d_in[3];
    const float* Wk   = (const float*)d_in[4];
    const float* bk   = (const float*)d_in[5];
    const float* Wv   = (const float*)d_in[6];
    const float* bv   = (const float*)d_in[7];
    const float* E    = (const float*)d_in[8];
    const float* Wo   = (const float*)d_in[9];
    const float* bo   = (const float*)d_in[10];
    float* out        = (float*)d_out;

    float *gQ, *gK, *gV, *gXo;
    cudaGetSymbolAddress((void**)&gQ,  g_Q);
    cudaGetSymbolAddress((void**)&gK,  g_K);
    cudaGetSymbolAddress((void**)&gV,  g_V);
    cudaGetSymbolAddress((void**)&gXo, g_Xo);

    // attention kernel needs >48KB dynamic smem
    static_assert(ATTN_SMEM_FLOATS * 4 < 227 * 1024, "smem");
    cudaFuncSetAttribute(attn_kernel, cudaFuncAttributeMaxDynamicSharedMemorySize,
                         ATTN_SMEM_FLOATS * 4);

    dim3 gg(Dv / 128, Mrows / 128);   // (8, 128)

    // Q / K / V projections (mask folded into K, V stores)
    sgemm_bias_kernel<<<gg, 256>>>(X, Wq, bq, nullptr, gQ, Mrows, Dv, Dv);
    sgemm_bias_kernel<<<gg, 256>>>(X, Wk, bk, mask,    gK, Mrows, Dv, Dv);
    sgemm_bias_kernel<<<gg, 256>>>(X, Wv, bv, mask,    gV, Mrows, Dv, Dv);

    // Kp / Vp = E @ (K*m), E @ (V*m)
    proj_kernel<<<dim3(LKv / 64, Bv * Hv, 2), 256>>>(E);

    // fused attention -> g_Xo
    attn_kernel<<<dim3(Sv / 64, Bv * Hv), 256, ATTN_SMEM_FLOATS * 4>>>();

    // output projection -> d_out
    sgemm_bias_kernel<<<gg, 256>>>(gXo, Wo, bo, nullptr, out, Mrows, Dv, Dv);
}

// round 4
// speedup vs baseline: 1.6811x; 1.6811x over previous
#include <cuda_runtime.h>
#include <cuda_bf16.h>
#include <math.h>

// Problem constants
#define Bv   4
#define Sv   4096
#define Dv   1024
#define Hv   16
#define HDv  64
#define LKv  256
#define Mrows (Bv*Sv)        // 16384

// ---------------- scratch (static device globals; no allocation allowed) ----
__device__ float g_Q [(long long)Mrows * Dv];   // 64 MB
__device__ float g_K [(long long)Mrows * Dv];   // 64 MB (already masked)
__device__ float g_V [(long long)Mrows * Dv];   // 64 MB (already masked)
__device__ float g_Xo[(long long)Mrows * Dv];   // 64 MB
__device__ float g_Kp[(long long)Bv * Hv * LKv * HDv];  // 16 MB
__device__ float g_Vp[(long long)Bv * Hv * LKv * HDv];  // 16 MB

// ---------------- bf16x3 helpers --------------------------------------------
__device__ __forceinline__ void bfsplit(float v, __nv_bfloat16& h, __nv_bfloat16& l) {
    h = __float2bfloat16(v);
    l = __float2bfloat16(v - __bfloat162float(h));
}
__device__ __forceinline__ unsigned pack2(__nv_bfloat16 a, __nv_bfloat16 b) {
    __nv_bfloat162 t = __halves2bfloat162(a, b);   // .x = a (low), .y = b (high)
    return *reinterpret_cast<unsigned*>(&t);
}

// D += A(16x16,row) * B(16x8,col)   (bf16 in, fp32 acc)
__device__ __forceinline__ void mma_bf16(float* d, const unsigned* a,
                                         const unsigned* b) {
    asm volatile(
        "mma.sync.aligned.m16n8k16.row.col.f32.bf16.bf16.f32 "
        "{%0,%1,%2,%3}, {%4,%5,%6,%7}, {%8,%9}, {%0,%1,%2,%3};\n"
        : "+f"(d[0]), "+f"(d[1]), "+f"(d[2]), "+f"(d[3])
        : "r"(a[0]), "r"(a[1]), "r"(a[2]), "r"(a[3]),
          "r"(b[0]), "r"(b[1]));
}

// ============================================================================
// bf16x3 GEMM: out[M,N] = A[M,K] @ W[K,N] + bias[N], optional per-row scale
// (applied AFTER bias — matches (X@Wk + bk) * mask).
// BM=128, BN=128, BK=16. 256 threads = 8 warps in 2(m) x 4(n); warp tile
// 64x32 -> 4 m-tiles x 4 n-tiles of m16n8k16. Each output gets 3 MMAs:
// hi*hi + hi*lo + lo*hi.
// Smem: A as [m][kpair] (hi,lo), B as [n][kpair] (hi,lo), stride 9 u32.
// ============================================================================
__global__ __launch_bounds__(256) void gemm_bf16x3(
    const float* __restrict__ A, const float* __restrict__ W,
    const float* __restrict__ bias, const float* __restrict__ rowscale,
    float* __restrict__ out, int M, int N, int K)
{
    __shared__ unsigned Ah[128][9], Al[128][9];   // [m][k/2]
    __shared__ unsigned Bh[128][9], Bl[128][9];   // [n][k/2]

    const int m0 = blockIdx.y * 128;
    const int n0 = blockIdx.x * 128;
    const int t    = threadIdx.x;
    const int lane = t & 31;
    const int warp = t >> 5;
    const int wm   = warp >> 2;        // 0..1  (m offset wm*64)
    const int wn   = warp & 3;         // 0..3  (n offset wn*32)
    const int gid  = lane >> 2;        // 0..7
    const int tig  = lane & 3;         // 0..3

    // A global-load mapping: rows arow, arow+64; cols acol..acol+3 (k)
    const int arow = t >> 2;            // 0..63
    const int acol = (t & 3) * 4;       // 0,4,8,12
    // B global-load mapping: k rows kb, kb+8; n = lane + 32*i (i=0..3)
    const int kb = warp;                // 0..7

    float4 ra0, ra1;
    float  rb[2][4];

    auto load_gmem = [&](int k0) {
        ra0 = *(const float4*)&A[(size_t)(m0 + arow)      * K + k0 + acol];
        ra1 = *(const float4*)&A[(size_t)(m0 + arow + 64) * K + k0 + acol];
        #pragma unroll
        for (int j = 0; j < 2; j++)
            #pragma unroll
            for (int i = 0; i < 4; i++)
                rb[j][i] = W[(size_t)(k0 + kb + 8 * j) * N + n0 + lane + 32 * i];
    };

    __nv_bfloat16* Bh16 = reinterpret_cast<__nv_bfloat16*>(&Bh[0][0]);
    __nv_bfloat16* Bl16 = reinterpret_cast<__nv_bfloat16*>(&Bl[0][0]);

    auto store_smem = [&]() {
        __nv_bfloat16 h0, l0, h1, l1, h2, l2, h3, l3;
        bfsplit(ra0.x, h0, l0); bfsplit(ra0.y, h1, l1);
        bfsplit(ra0.z, h2, l2); bfsplit(ra0.w, h3, l3);
        Ah[arow][acol / 2]     = pack2(h0, h1);
        Ah[arow][acol / 2 + 1] = pack2(h2, h3);
        Al[arow][acol / 2]     = pack2(l0, l1);
        Al[arow][acol / 2 + 1] = pack2(l2, l3);
        bfsplit(ra1.x, h0, l0); bfsplit(ra1.y, h1, l1);
        bfsplit(ra1.z, h2, l2); bfsplit(ra1.w, h3, l3);
        Ah[arow + 64][acol / 2]     = pack2(h0, h1);
        Ah[arow + 64][acol / 2 + 1] = pack2(h2, h3);
        Al[arow + 64][acol / 2]     = pack2(l0, l1);
        Al[arow + 64][acol / 2 + 1] = pack2(l2, l3);
        #pragma unroll
        for (int j = 0; j < 2; j++)
            #pragma unroll
            for (int i = 0; i < 4; i++) {
                __nv_bfloat16 h, l;
                bfsplit(rb[j][i], h, l);
                int n = lane + 32 * i;
                int k = kb + 8 * j;
                Bh16[n * 18 + k] = h;
                Bl16[n * 18 + k] = l;
            }
    };

    float acc[4][4][4];
    #pragma unroll
    for (int i = 0; i < 4; i++)
        #pragma unroll
        for (int j = 0; j < 4; j++)
            #pragma unroll
            for (int r = 0; r < 4; r++) acc[i][j][r] = 0.0f;

    load_gmem(0);
    store_smem();
    __syncthreads();

    for (int k0 = 0; k0 < K; k0 += 16) {
        const bool has_next = (k0 + 16) < K;
        if (has_next) load_gmem(k0 + 16);

        unsigned bh[4][2], bl[4][2];
        #pragma unroll
        for (int nt = 0; nt < 4; nt++) {
            const int n = wn * 32 + nt * 8 + gid;
            bh[nt][0] = Bh[n][tig];  bh[nt][1] = Bh[n][tig + 4];
            bl[nt][0] = Bl[n][tig];  bl[nt][1] = Bl[n][tig + 4];
        }
        #pragma unroll
        for (int mt = 0; mt < 4; mt++) {
            const int m = wm * 64 + mt * 16;
            unsigned ah[4], al[4];
            ah[0] = Ah[m + gid][tig];      ah[1] = Ah[m + gid + 8][tig];
            ah[2] = Ah[m + gid][tig + 4];  ah[3] = Ah[m + gid + 8][tig + 4];
            al[0] = Al[m + gid][tig];      al[1] = Al[m + gid + 8][tig];
            al[2] = Al[m + gid][tig + 4];  al[3] = Al[m + gid + 8][tig + 4];
            #pragma unroll
            for (int nt = 0; nt < 4; nt++) {
                mma_bf16(acc[mt][nt], ah, bh[nt]);   // hi*hi
                mma_bf16(acc[mt][nt], ah, bl[nt]);   // hi*lo
                mma_bf16(acc[mt][nt], al, bh[nt]);   // lo*hi
            }
        }
        __syncthreads();
        if (has_next) { store_smem(); __syncthreads(); }
    }

    // epilogue: bias (+ optional per-row mask scale)
    #pragma unroll
    for (int mt = 0; mt < 4; mt++) {
        const int r0 = m0 + wm * 64 + mt * 16 + gid;
        const float ms0 = rowscale ? rowscale[r0]     : 1.0f;
        const float ms1 = rowscale ? rowscale[r0 + 8] : 1.0f;
        #pragma unroll
        for (int nt = 0; nt < 4; nt++) {
            const int c = n0 + wn * 32 + nt * 8 + tig * 2;
            const float b0 = bias[c], b1 = bias[c + 1];
            float2 v0 = {(acc[mt][nt][0] + b0) * ms0, (acc[mt][nt][1] + b1) * ms0};
            float2 v1 = {(acc[mt][nt][2] + b0) * ms1, (acc[mt][nt][3] + b1) * ms1};
            *(float2*)&out[(size_t)r0       * N + c] = v0;
            *(float2*)&out[(size_t)(r0 + 8) * N + c] = v1;
        }
    }
}

// ============================================================================
// bf16x3 projection: Kp[b,h,k,d] = sum_s E[h,k,s] * Ksrc[b,s,h*64+d]
// Per (b,h,z): M=256(k), N=64(d), inner 4096(s).
// BM=128, BN=64, BK=16; 256 threads = 8 warps in 4(m) x 2(n); warp tile
// 32x32 -> 2 m-tiles x 4 n-tiles. grid = (LK/128=2, B*H=64, 2).
// ============================================================================
__global__ __launch_bounds__(256) void proj_bf16x3(const float* __restrict__ E)
{
    __shared__ unsigned Ah[128][9], Al[128][9];   // [k_lk][s/2]
    __shared__ unsigned Bh[64][9],  Bl[64][9];    // [d][s/2]

    const int m0 = blockIdx.x * 128;   // within LK
    const int bh = blockIdx.y;
    const int b  = bh >> 4;
    const int h  = bh & 15;
    const int z  = blockIdx.z;

    const float* src = z == 0 ? g_K : g_V;
    float*       dst = (z == 0 ? g_Kp : g_Vp) + (size_t)bh * LKv * HDv;

    const int t    = threadIdx.x;
    const int lane = t & 31;
    const int warp = t >> 5;
    const int wm   = warp >> 1;        // 0..3  (m offset wm*32)
    const int wn   = warp & 1;         // 0..1  (n offset wn*32)
    const int gid  = lane >> 2;
    const int tig  = lane & 3;

    const int arow = t >> 2;            // 0..63
    const int acol = (t & 3) * 4;       // k (s) within tile
    const int kb   = t >> 4;            // 0..15 (s row)
    const int nb   = t & 15;            // d base; d = nb + 16*i

    const float* Eb = E + ((size_t)h * LKv + m0) * Sv;
    const float* Kb = src + (size_t)b * Sv * Dv + h * HDv;

    float4 ra0, ra1;
    float  rb[4];

    auto load_gmem = [&](int s0) {
        ra0 = *(const float4*)&Eb[(size_t)(arow)      * Sv + s0 + acol];
        ra1 = *(const float4*)&Eb[(size_t)(arow + 64) * Sv + s0 + acol];
        #pragma unroll
        for (int i = 0; i < 4; i++)
            rb[i] = Kb[(size_t)(s0 + kb) * Dv + nb + 16 * i];
    };

    __nv_bfloat16* Bh16 = reinterpret_cast<__nv_bfloat16*>(&Bh[0][0]);
    __nv_bfloat16* Bl16 = reinterpret_cast<__nv_bfloat16*>(&Bl[0][0]);

    auto store_smem = [&]() {
        __nv_bfloat16 h0, l0, h1, l1, h2, l2, h3, l3;
        bfsplit(ra0.x, h0, l0); bfsplit(ra0.y, h1, l1);
        bfsplit(ra0.z, h2, l2); bfsplit(ra0.w, h3, l3);
        Ah[arow][acol / 2]     = pack2(h0, h1);
        Ah[arow][acol / 2 + 1] = pack2(h2, h3);
        Al[arow][acol / 2]     = pack2(l0, l1);
        Al[arow][acol / 2 + 1] = pack2(l2, l3);
        bfsplit(ra1.x, h0, l0); bfsplit(ra1.y, h1, l1);
        bfsplit(ra1.z, h2, l2); bfsplit(ra1.w, h3, l3);
        Ah[arow + 64][acol / 2]     = pack2(h0, h1);
        Ah[arow + 64][acol / 2 + 1] = pack2(h2, h3);
        Al[arow + 64][acol / 2]     = pack2(l0, l1);
        Al[arow + 64][acol / 2 + 1] = pack2(l2, l3);
        #pragma unroll
        for (int i = 0; i < 4; i++) {
            __nv_bfloat16 hh, ll;
            bfsplit(rb[i], hh, ll);
            int n = nb + 16 * i;
            Bh16[n * 18 + kb] = hh;
            Bl16[n * 18 + kb] = ll;
        }
    };

    float acc[2][4][4];
    #pragma unroll
    for (int i = 0; i < 2; i++)
        #pragma unroll
        for (int j = 0; j < 4; j++)
            #pragma unroll
            for (int r = 0; r < 4; r++) acc[i][j][r] = 0.0f;

    load_gmem(0);
    store_smem();
    __syncthreads();

    for (int s0 = 0; s0 < Sv; s0 += 16) {
        const bool has_next = (s0 + 16) < Sv;
        if (has_next) load_gmem(s0 + 16);

        unsigned bhf[4][2], blf[4][2];
        #pragma unroll
        for (int nt = 0; nt < 4; nt++) {
            const int n = wn * 32 + nt * 8 + gid;
            bhf[nt][0] = Bh[n][tig];  bhf[nt][1] = Bh[n][tig + 4];
            blf[nt][0] = Bl[n][tig];  blf[nt][1] = Bl[n][tig + 4];
        }
        #pragma unroll
        for (int mt = 0; mt < 2; mt++) {
            const int m = wm * 32 + mt * 16;
            unsigned ah[4], al[4];
            ah[0] = Ah[m + gid][tig];      ah[1] = Ah[m + gid + 8][tig];
            ah[2] = Ah[m + gid][tig + 4];  ah[3] = Ah[m + gid + 8][tig + 4];
            al[0] = Al[m + gid][tig];      al[1] = Al[m + gid + 8][tig];
            al[2] = Al[m + gid][tig + 4];  al[3] = Al[m + gid + 8][tig + 4];
            #pragma unroll
            for (int nt = 0; nt < 4; nt++) {
                mma_bf16(acc[mt][nt], ah, bhf[nt]);
                mma_bf16(acc[mt][nt], ah, blf[nt]);
                mma_bf16(acc[mt][nt], al, bhf[nt]);
            }
        }
        __syncthreads();
        if (has_next) { store_smem(); __syncthreads(); }
    }

    #pragma unroll
    for (int mt = 0; mt < 2; mt++) {
        const int k0 = m0 + wm * 32 + mt * 16 + gid;
        #pragma unroll
        for (int nt = 0; nt < 4; nt++) {
            const int d = wn * 32 + nt * 8 + tig * 2;
            float2 v0 = {acc[mt][nt][0], acc[mt][nt][1]};
            float2 v1 = {acc[mt][nt][2], acc[mt][nt][3]};
            *(float2*)&dst[(size_t)k0       * HDv + d] = v0;
            *(float2*)&dst[(size_t)(k0 + 8) * HDv + d] = v1;
        }
    }
}

// ============================================================================
// Fused attention (fp32, unchanged): per (b,h), stage Kp^T + Vp in smem,
// warp-per-row dot -> softmax(LK=256) -> weighted sum.
// ============================================================================
#define ATTN_SMEM_FLOATS (64*257 + 256*64 + 8*256 + 8*64)

__global__ __launch_bounds__(256) void attn_kernel()
{
    extern __shared__ float sm[];
    float* Kpt   = sm;                       // [64][257]
    float* Vps   = Kpt + 64 * 257;           // [256][64]
    float* attnb = Vps + 256 * 64;           // [8][256]
    float* qs    = attnb + 8 * 256;          // [8][64]

    const int bh   = blockIdx.y;
    const int b    = bh >> 4;
    const int h    = bh & 15;
    const int s0   = blockIdx.x * 64;
    const int t    = threadIdx.x;
    const int lane = t & 31;
    const int w    = t >> 5;

    const float* Kp = g_Kp + (size_t)bh * LKv * HDv;
    const float* Vp = g_Vp + (size_t)bh * LKv * HDv;

    #pragma unroll
    for (int i = 0; i < 64; i++) {
        int e = t + i * 256;
        int k = e >> 6, d = e & 63;
        Kpt[d * 257 + k] = Kp[e];
        Vps[e]           = Vp[e];
    }
    __syncthreads();

    const float* Qh = g_Q + (size_t)b * Sv * Dv + h * HDv;
    float* Oh       = g_Xo + (size_t)b * Sv * Dv + h * HDv;

    for (int r = 0; r < 8; r++) {
        const int s = s0 + w * 8 + r;
        const float* q = Qh + (size_t)s * Dv;
        qs[w * 64 + lane]      = q[lane];
        qs[w * 64 + lane + 32] = q[lane + 32];
        __syncwarp();

        float acc[8] = {0, 0, 0, 0, 0, 0, 0, 0};
        #pragma unroll 8
        for (int d = 0; d < 64; d++) {
            float qd = qs[w * 64 + d];
            #pragma unroll
            for (int jj = 0; jj < 8; jj++)
                acc[jj] = fmaf(qd, Kpt[d * 257 + jj * 32 + lane], acc[jj]);
        }

        float mx = -1e30f;
        #pragma unroll
        for (int jj = 0; jj < 8; jj++) { acc[jj] *= 0.125f; mx = fmaxf(mx, acc[jj]); }
        #pragma unroll
        for (int o = 16; o > 0; o >>= 1)
            mx = fmaxf(mx, __shfl_xor_sync(0xffffffffu, mx, o));
        float sum = 0.0f;
        #pragma unroll
        for (int jj = 0; jj < 8; jj++) { acc[jj] = __expf(acc[jj] - mx); sum += acc[jj]; }
        #pragma unroll
        for (int o = 16; o > 0; o >>= 1)
            sum += __shfl_xor_sync(0xffffffffu, sum, o);
        float inv = 1.0f / sum;
        #pragma unroll
        for (int jj = 0; jj < 8; jj++)
            attnb[w * 256 + jj * 32 + lane] = acc[jj] * inv;
        __syncwarp();

        float o0 = 0.0f, o1 = 0.0f;
        #pragma unroll 4
        for (int k = 0; k < 256; k++) {
            float a = attnb[w * 256 + k];
            o0 = fmaf(a, Vps[k * 64 + lane],      o0);
            o1 = fmaf(a, Vps[k * 64 + lane + 32], o1);
        }
        float* op = Oh + (size_t)s * Dv;
        op[lane]      = o0;
        op[lane + 32] = o1;
        __syncwarp();
    }
}

// ============================================================================
extern "C" void kernel_launch(void* const* d_in, const int* in_sizes, int n_in,
                              void* d_out, int out_size)
{
    const float* X    = (const float*)d_in[0];
    const float* mask = (const float*)d_in[1];
    const float* Wq   = (const float*)d_in[2];
    const float* bq   = (const float*)d_in[3];
    const float* Wk   = (const float*)d_in[4];
    const float* bk   = (const float*)d_in[5];
    const float* Wv   = (const float*)d_in[6];
    const float* bv   = (const float*)d_in[7];
    const float* E    = (const float*)d_in[8];
    const float* Wo   = (const float*)d_in[9];
    const float* bo   = (const float*)d_in[10];
    float* out        = (float*)d_out;

    float *gQ, *gK, *gV, *gXo;
    cudaGetSymbolAddress((void**)&gQ,  g_Q);
    cudaGetSymbolAddress((void**)&gK,  g_K);
    cudaGetSymbolAddress((void**)&gV,  g_V);
    cudaGetSymbolAddress((void**)&gXo, g_Xo);

    static_assert(ATTN_SMEM_FLOATS * 4 < 227 * 1024, "smem");
    cudaFuncSetAttribute(attn_kernel, cudaFuncAttributeMaxDynamicSharedMemorySize,
                         ATTN_SMEM_FLOATS * 4);

    dim3 gg(Dv / 128, Mrows / 128);   // (8, 128)

    // Q / K / V projections (bf16x3 tensor core; mask folded into K, V)
    gemm_bf16x3<<<gg, 256>>>(X, Wq, bq, nullptr, gQ, Mrows, Dv, Dv);
    gemm_bf16x3<<<gg, 256>>>(X, Wk, bk, mask,    gK, Mrows, Dv, Dv);
    gemm_bf16x3<<<gg, 256>>>(X, Wv, bv, mask,    gV, Mrows, Dv, Dv);

    // Kp / Vp = E @ (K*m), E @ (V*m)  (bf16x3 tensor core)
    proj_bf16x3<<<dim3(LKv / 128, Bv * Hv, 2), 256>>>(E);

    // fused attention -> g_Xo
    attn_kernel<<<dim3(Sv / 64, Bv * Hv), 256, ATTN_SMEM_FLOATS * 4>>>();

    // output projection -> d_out
    gemm_bf16x3<<<gg, 256>>>(gXo, Wo, bo, nullptr, out, Mrows, Dv, Dv);
}

// round 5
// speedup vs baseline: 1.7619x; 1.0480x over previous
#include <cuda_runtime.h>
#include <cuda_bf16.h>
#include <math.h>
#include <stdint.h>

// Problem constants
#define Bv   4
#define Sv   4096
#define Dv   1024
#define Hv   16
#define HDv  64
#define LKv  256
#define Mrows (Bv*Sv)                       // 16384
#define NELEM ((long long)Mrows * Dv)       // 16777216

typedef __nv_bfloat16 bf16;

// ---------------- scratch (static device globals; no allocation allowed) ----
__device__ bf16 g_Xhi[NELEM],  g_Xlo[NELEM];    // X split
__device__ bf16 g_Ehi[NELEM],  g_Elo[NELEM];    // E split (16*256*4096 == NELEM)
__device__ bf16 g_Wt_hi[4][(long long)Dv*Dv];   // Wq,Wk,Wv,Wo transposed [n][k]
__device__ bf16 g_Wt_lo[4][(long long)Dv*Dv];
__device__ bf16 g_Kt_hi[NELEM], g_Kt_lo[NELEM]; // K^T [b][d_global][s], masked
__device__ bf16 g_Vt_hi[NELEM], g_Vt_lo[NELEM];
__device__ bf16 g_XoHi[NELEM],  g_XoLo[NELEM];  // attn output split
__device__ float g_Q [NELEM];
__device__ float g_Xo[NELEM];
__device__ float g_Kp[(long long)Bv*Hv*LKv*HDv];
__device__ float g_Vp[(long long)Bv*Hv*LKv*HDv];

// ---------------- helpers ----------------------------------------------------
__device__ __forceinline__ void bfsplit(float v, bf16& h, bf16& l) {
    h = __float2bfloat16(v);
    l = __float2bfloat16(v - __bfloat162float(h));
}

// D += A(16x16,row) * B(16x8,col)   (bf16 in, fp32 acc)
__device__ __forceinline__ void mma_bf16(float* d, const unsigned* a,
                                         const unsigned* b) {
    asm volatile(
        "mma.sync.aligned.m16n8k16.row.col.f32.bf16.bf16.f32 "
        "{%0,%1,%2,%3}, {%4,%5,%6,%7}, {%8,%9}, {%0,%1,%2,%3};\n"
        : "+f"(d[0]), "+f"(d[1]), "+f"(d[2]), "+f"(d[3])
        : "r"(a[0]), "r"(a[1]), "r"(a[2]), "r"(a[3]),
          "r"(b[0]), "r"(b[1]));
}

__device__ __forceinline__ void ldsm4(unsigned& r0, unsigned& r1,
                                      unsigned& r2, unsigned& r3, unsigned addr) {
    asm volatile("ldmatrix.sync.aligned.m8n8.x4.shared.b16 {%0,%1,%2,%3}, [%4];\n"
                 : "=r"(r0), "=r"(r1), "=r"(r2), "=r"(r3) : "r"(addr));
}

__device__ __forceinline__ void cp16(unsigned dst, const void* src) {
    asm volatile("cp.async.cg.shared.global [%0], [%1], 16;\n" :: "r"(dst), "l"(src));
}
__device__ __forceinline__ void cp_commit() { asm volatile("cp.async.commit_group;\n"); }
__device__ __forceinline__ void cp_wait1()  { asm volatile("cp.async.wait_group 1;\n"); }
__device__ __forceinline__ void cp_wait0()  { asm volatile("cp.async.wait_group 0;\n"); }

// swizzle: 64B rows = 4 x 16B chunks; chunk' = chunk ^ ((row>>1)&3). result in 16B units
__device__ __forceinline__ unsigned swz16(int row, int chunk) {
    return (unsigned)(row * 4 + (chunk ^ ((row >> 1) & 3)));
}

// ============================================================================
// GEMM core: C[BMxBN] += (Ahi+Alo)[BMxK] * (Bhi+Blo)[BNxK]^T  (bf16x3 scheme)
// A rows: [m][k] stride K; B rows: [n][k] stride K (pre-transposed operand).
// BM=128, BK=32, 2-stage cp.async pipeline, ldmatrix fragment loads.
// Warps: WR x WC grid; warp tile (128/WR) x (BN/WC).
// ============================================================================
template<int BN, int WR, int WC>
__device__ __forceinline__ void gemm_core(
    const bf16* __restrict__ Ahg, const bf16* __restrict__ Alg,
    const bf16* __restrict__ Bhg, const bf16* __restrict__ Blg,
    int K,
    float (&acc)[(128/WR)/16][(BN/WC)/8][4])
{
    constexpr int BM = 128, BK = 32;
    constexpr int MT = (BM/WR)/16;
    constexpr int NT = (BN/WC)/8;
    constexpr int A_ELE = BM*BK, B_ELE = BN*BK;
    constexpr unsigned OF_AL = A_ELE*2;                 // byte offsets within stage
    constexpr unsigned OF_BH = 2*A_ELE*2;
    constexpr unsigned OF_BL = (2*A_ELE+B_ELE)*2;
    constexpr unsigned STAGE_B = (2*A_ELE+2*B_ELE)*2;

    extern __shared__ bf16 smem_dyn[];
    const unsigned s0 = (unsigned)__cvta_generic_to_shared(smem_dyn);

    const int t = threadIdx.x, lane = t & 31, warp = t >> 5;
    const int wm = warp / WC, wn = warp % WC;
    const int m_w = wm * (BM/WR), n_w = wn * (BN/WC);

    // -------- cp.async mappings --------
    const int a_row = t >> 1;                 // 0..127, 2 chunks each
    const int a_c0  = (t & 1) * 2;
    const unsigned a_d0 = swz16(a_row, a_c0)     * 16;
    const unsigned a_d1 = swz16(a_row, a_c0 + 1) * 16;

    int b_row, b_c0;
    if (BN == 128) { b_row = t >> 1; b_c0 = (t & 1) * 2; }
    else           { b_row = t >> 2; b_c0 = t & 3; }
    const unsigned b_d0 = swz16(b_row, b_c0) * 16;
    const unsigned b_d1 = (BN == 128) ? swz16(b_row, b_c0 + 1) * 16 : 0;

    auto issue = [&](int st, int k0) {
        const unsigned sb = s0 + st * STAGE_B;
        const char* pah = (const char*)(Ahg + (size_t)a_row * K + k0);
        const char* pal = (const char*)(Alg + (size_t)a_row * K + k0);
        cp16(sb + a_d0,         pah + a_c0*16);
        cp16(sb + a_d1,         pah + a_c0*16 + 16);
        cp16(sb + OF_AL + a_d0, pal + a_c0*16);
        cp16(sb + OF_AL + a_d1, pal + a_c0*16 + 16);
        const char* pbh = (const char*)(Bhg + (size_t)b_row * K + k0);
        const char* pbl = (const char*)(Blg + (size_t)b_row * K + k0);
        cp16(sb + OF_BH + b_d0, pbh + b_c0*16);
        cp16(sb + OF_BL + b_d0, pbl + b_c0*16);
        if (BN == 128) {
            cp16(sb + OF_BH + b_d1, pbh + b_c0*16 + 16);
            cp16(sb + OF_BL + b_d1, pbl + b_c0*16 + 16);
        }
    };

    // -------- ldmatrix fragment addresses (per-thread constants) --------
    const int lr  = lane & 7;
    const int aLR = lr + ((lane >> 3) & 1) * 8;   // row within 16-row A matrix group
    const int aLC = lane >> 4;                    // k-chunk select (j>>1)
    unsigned adA[MT][2];
    #pragma unroll
    for (int mt = 0; mt < MT; mt++)
        #pragma unroll
        for (int ks = 0; ks < 2; ks++) {
            int row = m_w + mt*16 + aLR;
            adA[mt][ks] = swz16(row, 2*ks + aLC) * 16;
        }
    const int j   = lane >> 3;
    const int bLR = ((j >> 1) & 1) * 8 + lr;      // row within 16-row B matrix group
    const int bLC = j & 1;                        // k-chunk select
    unsigned adB[NT/2][2];
    #pragma unroll
    for (int p = 0; p < NT/2; p++)
        #pragma unroll
        for (int ks = 0; ks < 2; ks++) {
            int row = n_w + p*16 + bLR;
            adB[p][ks] = swz16(row, 2*ks + bLC) * 16;
        }

    // -------- pipelined mainloop --------
    const int ntiles = K / BK;
    issue(0, 0); cp_commit();

    for (int i = 0; i < ntiles; i++) {
        if (i + 1 < ntiles) { issue((i+1)&1, (i+1)*BK); cp_commit(); cp_wait1(); }
        else                { cp_wait0(); }
        __syncthreads();

        const unsigned sb = s0 + (i & 1) * STAGE_B;
        #pragma unroll
        for (int ks = 0; ks < 2; ks++) {
            unsigned bh[NT][2], bl[NT][2];
            #pragma unroll
            for (int p = 0; p < NT/2; p++) {
                ldsm4(bh[2*p][0], bh[2*p][1], bh[2*p+1][0], bh[2*p+1][1],
                      sb + OF_BH + adB[p][ks]);
                ldsm4(bl[2*p][0], bl[2*p][1], bl[2*p+1][0], bl[2*p+1][1],
                      sb + OF_BL + adB[p][ks]);
            }
            #pragma unroll
            for (int mt = 0; mt < MT; mt++) {
                unsigned ah[4], al[4];
                ldsm4(ah[0], ah[1], ah[2], ah[3], sb + adA[mt][ks]);
                ldsm4(al[0], al[1], al[2], al[3], sb + OF_AL + adA[mt][ks]);
                #pragma unroll
                for (int nt = 0; nt < NT; nt++) {
                    mma_bf16(acc[mt][nt], ah, bh[nt]);   // hi*hi
                    mma_bf16(acc[mt][nt], ah, bl[nt]);   // hi*lo
                    mma_bf16(acc[mt][nt], al, bh[nt]);   // lo*hi
                }
            }
        }
        __syncthreads();
    }
}

// ============================================================================
// Main GEMM wrapper. OUT_MODE 0: fp32 out[m][n] = acc + bias (xrowscale).
// OUT_MODE 1: bf16 hi/lo split, stored TRANSPOSED as Kt[b][n][s] (for proj).
// ============================================================================
template<int OUT_MODE>
__global__ __launch_bounds__(256) void gemm_main(
    const bf16* __restrict__ Ahi, const bf16* __restrict__ Alo,
    const bf16* __restrict__ Bhi, const bf16* __restrict__ Blo,
    const float* __restrict__ bias, const float* __restrict__ rowscale,
    float* __restrict__ outf, bf16* __restrict__ oThi, bf16* __restrict__ oTlo,
    int N, int K)
{
    const int m0 = blockIdx.y * 128, n0 = blockIdx.x * 128;
    float acc[4][4][4];
    #pragma unroll
    for (int a = 0; a < 4; a++)
        #pragma unroll
        for (int b = 0; b < 4; b++)
            #pragma unroll
            for (int c = 0; c < 4; c++) acc[a][b][c] = 0.0f;

    gemm_core<128, 2, 4>(Ahi + (size_t)m0 * K, Alo + (size_t)m0 * K,
                         Bhi + (size_t)n0 * K, Blo + (size_t)n0 * K, K, acc);

    const int lane = threadIdx.x & 31, warp = threadIdx.x >> 5;
    const int wm = warp >> 2, wn = warp & 3;
    const int gid = lane >> 2, tig = lane & 3;

    #pragma unroll
    for (int mt = 0; mt < 4; mt++) {
        const int r0 = m0 + wm * 64 + mt * 16 + gid;
        const float ms0 = rowscale ? rowscale[r0]     : 1.0f;
        const float ms1 = rowscale ? rowscale[r0 + 8] : 1.0f;
        #pragma unroll
        for (int nt = 0; nt < 4; nt++) {
            const int c = n0 + wn * 32 + nt * 8 + tig * 2;
            const float b0 = bias[c], b1 = bias[c + 1];
            float v00 = (acc[mt][nt][0] + b0) * ms0;
            float v01 = (acc[mt][nt][1] + b1) * ms0;
            float v10 = (acc[mt][nt][2] + b0) * ms1;
            float v11 = (acc[mt][nt][3] + b1) * ms1;
            if (OUT_MODE == 0) {
                *(float2*)&outf[(size_t)r0       * N + c] = make_float2(v00, v01);
                *(float2*)&outf[(size_t)(r0 + 8) * N + c] = make_float2(v10, v11);
            } else {
                // transposed split store: addr(m,n) = (m>>12)*2^22 + n*4096 + (m&4095)
                const int rr[2] = {r0, r0 + 8};
                const float vv[2][2] = {{v00, v01}, {v10, v11}};
                #pragma unroll
                for (int i = 0; i < 2; i++)
                    #pragma unroll
                    for (int q = 0; q < 2; q++) {
                        size_t ad = ((size_t)(rr[i] >> 12) << 22)
                                  + (size_t)(c + q) * 4096 + (rr[i] & 4095);
                        bf16 h, l; bfsplit(vv[i][q], h, l);
                        oThi[ad] = h; oTlo[ad] = l;
                    }
            }
        }
    }
}

// ============================================================================
// Projection: Kp[bh][lk][d] = sum_s E[h][lk][s] * Kt[b][h*64+d][s]
// grid = (LK/128=2, B*H=64, 2{K,V}); BM=128, BN=64, warps 4x2.
// ============================================================================
__global__ __launch_bounds__(256) void proj_tc()
{
    const int m0 = blockIdx.x * 128;
    const int bh = blockIdx.y;
    const int b  = bh >> 4, h = bh & 15;
    const int z  = blockIdx.z;

    const bf16* Ah = g_Ehi + ((size_t)h * LKv + m0) * Sv;
    const bf16* Al = g_Elo + ((size_t)h * LKv + m0) * Sv;
    const size_t boff = (size_t)(b * Dv + h * HDv) * Sv;
    const bf16* Bh = (z ? g_Vt_hi : g_Kt_hi) + boff;
    const bf16* Bl = (z ? g_Vt_lo : g_Kt_lo) + boff;
    float* out = (z ? g_Vp : g_Kp) + (size_t)bh * LKv * HDv;

    float acc[2][4][4];
    #pragma unroll
    for (int a = 0; a < 2; a++)
        #pragma unroll
        for (int c = 0; c < 4; c++)
            #pragma unroll
            for (int r = 0; r < 4; r++) acc[a][c][r] = 0.0f;

    gemm_core<64, 4, 2>(Ah, Al, Bh, Bl, Sv, acc);

    const int lane = threadIdx.x & 31, warp = threadIdx.x >> 5;
    const int wm = warp >> 1, wn = warp & 1;
    const int gid = lane >> 2, tig = lane & 3;

    #pragma unroll
    for (int mt = 0; mt < 2; mt++) {
        const int r0 = m0 + wm * 32 + mt * 16 + gid;
        #pragma unroll
        for (int nt = 0; nt < 4; nt++) {
            const int c = wn * 32 + nt * 8 + tig * 2;
            *(float2*)&out[(size_t)r0       * HDv + c] =
                make_float2(acc[mt][nt][0], acc[mt][nt][1]);
            *(float2*)&out[(size_t)(r0 + 8) * HDv + c] =
                make_float2(acc[mt][nt][2], acc[mt][nt][3]);
        }
    }
}

// ============================================================================
// Prepass: fp32 -> bf16 hi/lo split (elementwise)
// ============================================================================
__global__ void split_k(const float* __restrict__ in, bf16* __restrict__ hi,
                        bf16* __restrict__ lo, int n4)
{
    int i = (blockIdx.x * blockDim.x + threadIdx.x);
    if (i >= n4) return;
    float4 v = *(const float4*)&in[i * 4];
    bf16 h0, l0, h1, l1, h2, l2, h3, l3;
    bfsplit(v.x, h0, l0); bfsplit(v.y, h1, l1);
    bfsplit(v.z, h2, l2); bfsplit(v.w, h3, l3);
    __nv_bfloat162* ph = (__nv_bfloat162*)&hi[i * 4];
    __nv_bfloat162* pl = (__nv_bfloat162*)&lo[i * 4];
    ph[0] = __halves2bfloat162(h0, h1); ph[1] = __halves2bfloat162(h2, h3);
    pl[0] = __halves2bfloat162(l0, l1); pl[1] = __halves2bfloat162(l2, l3);
}

// Prepass: W[K=1024][N=1024] -> Wt hi/lo [N][K]  (transpose + split)
__global__ void tsplit_k(const float* __restrict__ in, bf16* __restrict__ hi,
                         bf16* __restrict__ lo)
{
    __shared__ float ts[32][33];
    const int bx = blockIdx.x * 32, by = blockIdx.y * 32;  // bx: n, by: k
    const int tx = threadIdx.x, ty = threadIdx.y;          // 32 x 8
    #pragma unroll
    for (int j = 0; j < 4; j++)
        ts[ty + j * 8][tx] = in[(size_t)(by + ty + j * 8) * Dv + bx + tx];
    __syncthreads();
    #pragma unroll
    for (int j = 0; j < 4; j++) {
        float v = ts[tx][ty + j * 8];
        bf16 h, l; bfsplit(v, h, l);
        size_t ad = (size_t)(bx + ty + j * 8) * Dv + by + tx;
        hi[ad] = h; lo[ad] = l;
    }
}

// ============================================================================
// Fused attention (fp32, unchanged): per (b,h), stage Kp^T + Vp in smem,
// warp-per-row dot -> softmax(LK=256) -> weighted sum.
// ============================================================================
#define ATTN_SMEM_FLOATS (64*257 + 256*64 + 8*256 + 8*64)

__global__ __launch_bounds__(256) void attn_kernel()
{
    extern __shared__ float sm[];
    float* Kpt   = sm;                       // [64][257]
    float* Vps   = Kpt + 64 * 257;           // [256][64]
    float* attnb = Vps + 256 * 64;           // [8][256]
    float* qs    = attnb + 8 * 256;          // [8][64]

    const int bh   = blockIdx.y;
    const int b    = bh >> 4;
    const int h    = bh & 15;
    const int s0   = blockIdx.x * 64;
    const int t    = threadIdx.x;
    const int lane = t & 31;
    const int w    = t >> 5;

    const float* Kp = g_Kp + (size_t)bh * LKv * HDv;
    const float* Vp = g_Vp + (size_t)bh * LKv * HDv;

    #pragma unroll
    for (int i = 0; i < 64; i++) {
        int e = t + i * 256;
        int k = e >> 6, d = e & 63;
        Kpt[d * 257 + k] = Kp[e];
        Vps[e]           = Vp[e];
    }
    __syncthreads();

    const float* Qh = g_Q + (size_t)b * Sv * Dv + h * HDv;
    float* Oh       = g_Xo + (size_t)b * Sv * Dv + h * HDv;

    for (int r = 0; r < 8; r++) {
        const int s = s0 + w * 8 + r;
        const float* q = Qh + (size_t)s * Dv;
        qs[w * 64 + lane]      = q[lane];
        qs[w * 64 + lane + 32] = q[lane + 32];
        __syncwarp();

        float acc[8] = {0, 0, 0, 0, 0, 0, 0, 0};
        #pragma unroll 8
        for (int d = 0; d < 64; d++) {
            float qd = qs[w * 64 + d];
            #pragma unroll
            for (int jj = 0; jj < 8; jj++)
                acc[jj] = fmaf(qd, Kpt[d * 257 + jj * 32 + lane], acc[jj]);
        }

        float mx = -1e30f;
        #pragma unroll
        for (int jj = 0; jj < 8; jj++) { acc[jj] *= 0.125f; mx = fmaxf(mx, acc[jj]); }
        #pragma unroll
        for (int o = 16; o > 0; o >>= 1)
            mx = fmaxf(mx, __shfl_xor_sync(0xffffffffu, mx, o));
        float sum = 0.0f;
        #pragma unroll
        for (int jj = 0; jj < 8; jj++) { acc[jj] = __expf(acc[jj] - mx); sum += acc[jj]; }
        #pragma unroll
        for (int o = 16; o > 0; o >>= 1)
            sum += __shfl_xor_sync(0xffffffffu, sum, o);
        float inv = 1.0f / sum;
        #pragma unroll
        for (int jj = 0; jj < 8; jj++)
            attnb[w * 256 + jj * 32 + lane] = acc[jj] * inv;
        __syncwarp();

        float o0 = 0.0f, o1 = 0.0f;
        #pragma unroll 4
        for (int k = 0; k < 256; k++) {
            float a = attnb[w * 256 + k];
            o0 = fmaf(a, Vps[k * 64 + lane],      o0);
            o1 = fmaf(a, Vps[k * 64 + lane + 32], o1);
        }
        float* op = Oh + (size_t)s * Dv;
        op[lane]      = o0;
        op[lane + 32] = o1;
        __syncwarp();
    }
}

// ============================================================================
extern "C" void kernel_launch(void* const* d_in, const int* in_sizes, int n_in,
                              void* d_out, int out_size)
{
    const float* X    = (const float*)d_in[0];
    const float* mask = (const float*)d_in[1];
    const float* Wq   = (const float*)d_in[2];
    const float* bq   = (const float*)d_in[3];
    const float* Wk   = (const float*)d_in[4];
    const float* bk   = (const float*)d_in[5];
    const float* Wv   = (const float*)d_in[6];
    const float* bv   = (const float*)d_in[7];
    const float* E    = (const float*)d_in[8];
    const float* Wo   = (const float*)d_in[9];
    const float* bo   = (const float*)d_in[10];
    float* out        = (float*)d_out;

    bf16 *xhi, *xlo, *ehi, *elo, *wth, *wtl, *kth, *ktl, *vth, *vtl, *xoh, *xol;
    float *gQ, *gXo;
    cudaGetSymbolAddress((void**)&xhi, g_Xhi);  cudaGetSymbolAddress((void**)&xlo, g_Xlo);
    cudaGetSymbolAddress((void**)&ehi, g_Ehi);  cudaGetSymbolAddress((void**)&elo, g_Elo);
    cudaGetSymbolAddress((void**)&wth, g_Wt_hi);cudaGetSymbolAddress((void**)&wtl, g_Wt_lo);
    cudaGetSymbolAddress((void**)&kth, g_Kt_hi);cudaGetSymbolAddress((void**)&ktl, g_Kt_lo);
    cudaGetSymbolAddress((void**)&vth, g_Vt_hi);cudaGetSymbolAddress((void**)&vtl, g_Vt_lo);
    cudaGetSymbolAddress((void**)&xoh, g_XoHi); cudaGetSymbolAddress((void**)&xol, g_XoLo);
    cudaGetSymbolAddress((void**)&gQ,  g_Q);    cudaGetSymbolAddress((void**)&gXo, g_Xo);

    const long long WSZ = (long long)Dv * Dv;   // 1M elements per weight

    // smem attributes
    cudaFuncSetAttribute(gemm_main<0>, cudaFuncAttributeMaxDynamicSharedMemorySize, 65536);
    cudaFuncSetAttribute(gemm_main<1>, cudaFuncAttributeMaxDynamicSharedMemorySize, 65536);
    cudaFuncSetAttribute(proj_tc,      cudaFuncAttributeMaxDynamicSharedMemorySize, 49152);
    cudaFuncSetAttribute(attn_kernel,  cudaFuncAttributeMaxDynamicSharedMemorySize,
                         ATTN_SMEM_FLOATS * 4);

    // -------- prepass: splits + weight transposes --------
    split_k<<<(int)(NELEM/4/256), 256>>>(X, xhi, xlo, (int)(NELEM/4));
    split_k<<<(int)(NELEM/4/256), 256>>>(E, ehi, elo, (int)(NELEM/4));
    tsplit_k<<<dim3(32,32), dim3(32,8)>>>(Wq, wth + 0*WSZ, wtl + 0*WSZ);
    tsplit_k<<<dim3(32,32), dim3(32,8)>>>(Wk, wth + 1*WSZ, wtl + 1*WSZ);
    tsplit_k<<<dim3(32,32), dim3(32,8)>>>(Wv, wth + 2*WSZ, wtl + 2*WSZ);
    tsplit_k<<<dim3(32,32), dim3(32,8)>>>(Wo, wth + 3*WSZ, wtl + 3*WSZ);

    dim3 gg(Dv / 128, Mrows / 128);   // (8, 128)

    // -------- QKV projections --------
    gemm_main<0><<<gg, 256, 65536>>>(xhi, xlo, wth + 0*WSZ, wtl + 0*WSZ,
                                     bq, nullptr, gQ, nullptr, nullptr, Dv, Dv);
    gemm_main<1><<<gg, 256, 65536>>>(xhi, xlo, wth + 1*WSZ, wtl + 1*WSZ,
                                     bk, mask, nullptr, kth, ktl, Dv, Dv);
    gemm_main<1><<<gg, 256, 65536>>>(xhi, xlo, wth + 2*WSZ, wtl + 2*WSZ,
                                     bv, mask, nullptr, vth, vtl, Dv, Dv);

    // -------- Kp / Vp = E @ (K*m), E @ (V*m) --------
    proj_tc<<<dim3(LKv/128, Bv*Hv, 2), 256, 49152>>>();

    // -------- fused attention -> g_Xo --------
    attn_kernel<<<dim3(Sv/64, Bv*Hv), 256, ATTN_SMEM_FLOATS * 4>>>();

    // -------- output projection -> d_out --------
    split_k<<<(int)(NELEM/4/256), 256>>>(gXo, xoh, xol, (int)(NELEM/4));
    gemm_main<0><<<gg, 256, 65536>>>(xoh, xol, wth + 3*WSZ, wtl + 3*WSZ,
                                     bo, nullptr, out, nullptr, nullptr, Dv, Dv);
}

// round 7
// speedup vs baseline: 2.9416x; 1.6696x over previous
#include <cuda_runtime.h>
#include <cuda_bf16.h>
#include <math.h>
#include <stdint.h>

// Problem constants
#define Bv   4
#define Sv   4096
#define Dv   1024
#define Hv   16
#define HDv  64
#define LKv  256
#define Mrows (Bv*Sv)                       // 16384
#define NELEM ((long long)Mrows * Dv)       // 16777216

typedef __nv_bfloat16 bf16;

// ---------------- scratch (static device globals; no allocation allowed) ----
__device__ bf16 g_Xhi[NELEM],  g_Xlo[NELEM];    // X split
__device__ bf16 g_Ehi[NELEM],  g_Elo[NELEM];    // E split
__device__ bf16 g_Wt_hi[4][(long long)Dv*Dv];   // Wq,Wk,Wv,Wo transposed [n][k]
__device__ bf16 g_Wt_lo[4][(long long)Dv*Dv];
__device__ bf16 g_Kt_hi[NELEM], g_Kt_lo[NELEM]; // K^T [b][d_global][s], masked
__device__ bf16 g_Vt_hi[NELEM], g_Vt_lo[NELEM];
__device__ bf16 g_XoHi[NELEM],  g_XoLo[NELEM];  // attn output split (row-major)
__device__ float g_Q [NELEM];                   // fp32 Q (row-major)
__device__ float g_Kp [(long long)Bv*Hv*LKv*HDv];  // Kp [bh][lk][d]
__device__ float g_VpT[(long long)Bv*Hv*HDv*LKv];  // Vp^T [bh][d][lk]

// ---------------- helpers ----------------------------------------------------
__device__ __forceinline__ void bfsplit(float v, bf16& h, bf16& l) {
    h = __float2bfloat16(v);
    l = __float2bfloat16(v - __bfloat162float(h));
}
__device__ __forceinline__ unsigned pack2(bf16 a, bf16 b) {
    __nv_bfloat162 t = __halves2bfloat162(a, b);
    return *reinterpret_cast<unsigned*>(&t);
}

// D += A(16x16,row) * B(16x8,col)   (bf16 in, fp32 acc)
__device__ __forceinline__ void mma_bf16(float* d, const unsigned* a,
                                         const unsigned* b) {
    asm volatile(
        "mma.sync.aligned.m16n8k16.row.col.f32.bf16.bf16.f32 "
        "{%0,%1,%2,%3}, {%4,%5,%6,%7}, {%8,%9}, {%0,%1,%2,%3};\n"
        : "+f"(d[0]), "+f"(d[1]), "+f"(d[2]), "+f"(d[3])
        : "r"(a[0]), "r"(a[1]), "r"(a[2]), "r"(a[3]),
          "r"(b[0]), "r"(b[1]));
}

__device__ __forceinline__ void ldsm4(unsigned& r0, unsigned& r1,
                                      unsigned& r2, unsigned& r3, unsigned addr) {
    asm volatile("ldmatrix.sync.aligned.m8n8.x4.shared.b16 {%0,%1,%2,%3}, [%4];\n"
                 : "=r"(r0), "=r"(r1), "=r"(r2), "=r"(r3) : "r"(addr));
}

__device__ __forceinline__ void cp16(unsigned dst, const void* src) {
    asm volatile("cp.async.cg.shared.global [%0], [%1], 16;\n" :: "r"(dst), "l"(src));
}
__device__ __forceinline__ void cp_commit() { asm volatile("cp.async.commit_group;\n"); }
__device__ __forceinline__ void cp_wait1()  { asm volatile("cp.async.wait_group 1;\n"); }
__device__ __forceinline__ void cp_wait0()  { asm volatile("cp.async.wait_group 0;\n"); }

// swizzle for 64B rows (gemm core): chunk' = chunk ^ ((row>>1)&3), in 16B units
__device__ __forceinline__ unsigned swz16(int row, int chunk) {
    return (unsigned)(row * 4 + (chunk ^ ((row >> 1) & 3)));
}

// ============================================================================
// GEMM core (mma.sync): C[128xBN] += (Ahi+Alo)[128,K]*(Bhi+Blo)[BN,K]^T
// bf16x3. BK=32, 2-stage cp.async pipeline, ldmatrix fragment loads.
// ============================================================================
template<int BN, int WR, int WC>
__device__ __forceinline__ void gemm_core(
    const bf16* __restrict__ Ahg, const bf16* __restrict__ Alg,
    const bf16* __restrict__ Bhg, const bf16* __restrict__ Blg,
    int K,
    float (&acc)[(128/WR)/16][(BN/WC)/8][4])
{
    constexpr int BM = 128, BK = 32;
    constexpr int MT = (BM/WR)/16;
    constexpr int NT = (BN/WC)/8;
    constexpr int A_ELE = BM*BK, B_ELE = BN*BK;
    constexpr unsigned OF_AL = A_ELE*2;
    constexpr unsigned OF_BH = 2*A_ELE*2;
    constexpr unsigned OF_BL = (2*A_ELE+B_ELE)*2;
    constexpr unsigned STAGE_B = (2*A_ELE+2*B_ELE)*2;

    extern __shared__ bf16 smem_dyn[];
    const unsigned s0 = (unsigned)__cvta_generic_to_shared(smem_dyn);

    const int t = threadIdx.x, lane = t & 31, warp = t >> 5;
    const int wm = warp / WC, wn = warp % WC;
    const int m_w = wm * (BM/WR), n_w = wn * (BN/WC);

    const int a_row = t >> 1;
    const int a_c0  = (t & 1) * 2;
    const unsigned a_d0 = swz16(a_row, a_c0)     * 16;
    const unsigned a_d1 = swz16(a_row, a_c0 + 1) * 16;

    int b_row, b_c0;
    if (BN == 128) { b_row = t >> 1; b_c0 = (t & 1) * 2; }
    else           { b_row = t >> 2; b_c0 = t & 3; }
    const unsigned b_d0 = swz16(b_row, b_c0) * 16;
    const unsigned b_d1 = (BN == 128) ? swz16(b_row, b_c0 + 1) * 16 : 0;

    auto issue = [&](int st, int k0) {
        const unsigned sb = s0 + st * STAGE_B;
        const char* pah = (const char*)(Ahg + (size_t)a_row * K + k0);
        const char* pal = (const char*)(Alg + (size_t)a_row * K + k0);
        cp16(sb + a_d0,         pah + a_c0*16);
        cp16(sb + a_d1,         pah + a_c0*16 + 16);
        cp16(sb + OF_AL + a_d0, pal + a_c0*16);
        cp16(sb + OF_AL + a_d1, pal + a_c0*16 + 16);
        const char* pbh = (const char*)(Bhg + (size_t)b_row * K + k0);
        const char* pbl = (const char*)(Blg + (size_t)b_row * K + k0);
        cp16(sb + OF_BH + b_d0, pbh + b_c0*16);
        cp16(sb + OF_BL + b_d0, pbl + b_c0*16);
        if (BN == 128) {
            cp16(sb + OF_BH + b_d1, pbh + b_c0*16 + 16);
            cp16(sb + OF_BL + b_d1, pbl + b_c0*16 + 16);
        }
    };

    const int lr  = lane & 7;
    const int aLR = lr + ((lane >> 3) & 1) * 8;
    const int aLC = lane >> 4;
    unsigned adA[MT][2];
    #pragma unroll
    for (int mt = 0; mt < MT; mt++)
        #pragma unroll
        for (int ks = 0; ks < 2; ks++) {
            int row = m_w + mt*16 + aLR;
            adA[mt][ks] = swz16(row, 2*ks + aLC) * 16;
        }
    const int j   = lane >> 3;
    const int bLR = ((j >> 1) & 1) * 8 + lr;
    const int bLC = j & 1;
    unsigned adB[NT/2][2];
    #pragma unroll
    for (int p = 0; p < NT/2; p++)
        #pragma unroll
        for (int ks = 0; ks < 2; ks++) {
            int row = n_w + p*16 + bLR;
            adB[p][ks] = swz16(row, 2*ks + bLC) * 16;
        }

    const int ntiles = K / BK;
    issue(0, 0); cp_commit();

    for (int i = 0; i < ntiles; i++) {
        if (i + 1 < ntiles) { issue((i+1)&1, (i+1)*BK); cp_commit(); cp_wait1(); }
        else                { cp_wait0(); }
        __syncthreads();

        const unsigned sb = s0 + (i & 1) * STAGE_B;
        #pragma unroll
        for (int ks = 0; ks < 2; ks++) {
            unsigned bh[NT][2], bl[NT][2];
            #pragma unroll
            for (int p = 0; p < NT/2; p++) {
                ldsm4(bh[2*p][0], bh[2*p][1], bh[2*p+1][0], bh[2*p+1][1],
                      sb + OF_BH + adB[p][ks]);
                ldsm4(bl[2*p][0], bl[2*p][1], bl[2*p+1][0], bl[2*p+1][1],
                      sb + OF_BL + adB[p][ks]);
            }
            #pragma unroll
            for (int mt = 0; mt < MT; mt++) {
                unsigned ah[4], al[4];
                ldsm4(ah[0], ah[1], ah[2], ah[3], sb + adA[mt][ks]);
                ldsm4(al[0], al[1], al[2], al[3], sb + OF_AL + adA[mt][ks]);
                #pragma unroll
                for (int nt = 0; nt < NT; nt++) {
                    mma_bf16(acc[mt][nt], ah, bh[nt]);
                    mma_bf16(acc[mt][nt], ah, bl[nt]);
                    mma_bf16(acc[mt][nt], al, bh[nt]);
                }
            }
        }
        __syncthreads();
    }
}

// ============================================================================
// Main GEMM. OUT_MODE 0: fp32 out = acc + bias (xrowscale).
// OUT_MODE 1: bf16 hi/lo split stored TRANSPOSED as Kt[b][n][s].
// ============================================================================
template<int OUT_MODE>
__global__ __launch_bounds__(256) void gemm_main(
    const bf16* __restrict__ Ahi, const bf16* __restrict__ Alo,
    const bf16* __restrict__ Bhi, const bf16* __restrict__ Blo,
    const float* __restrict__ bias, const float* __restrict__ rowscale,
    float* __restrict__ outf, bf16* __restrict__ oThi, bf16* __restrict__ oTlo,
    int N, int K)
{
    const int m0 = blockIdx.y * 128, n0 = blockIdx.x * 128;
    float acc[4][4][4];
    #pragma unroll
    for (int a = 0; a < 4; a++)
        #pragma unroll
        for (int b = 0; b < 4; b++)
            #pragma unroll
            for (int c = 0; c < 4; c++) acc[a][b][c] = 0.0f;

    gemm_core<128, 2, 4>(Ahi + (size_t)m0 * K, Alo + (size_t)m0 * K,
                         Bhi + (size_t)n0 * K, Blo + (size_t)n0 * K, K, acc);

    const int lane = threadIdx.x & 31, warp = threadIdx.x >> 5;
    const int wm = warp >> 2, wn = warp & 3;
    const int gid = lane >> 2, tig = lane & 3;

    #pragma unroll
    for (int mt = 0; mt < 4; mt++) {
        const int r0 = m0 + wm * 64 + mt * 16 + gid;
        const float ms0 = rowscale ? rowscale[r0]     : 1.0f;
        const float ms1 = rowscale ? rowscale[r0 + 8] : 1.0f;
        #pragma unroll
        for (int nt = 0; nt < 4; nt++) {
            const int c = n0 + wn * 32 + nt * 8 + tig * 2;
            const float b0 = bias[c], b1 = bias[c + 1];
            float v00 = (acc[mt][nt][0] + b0) * ms0;
            float v01 = (acc[mt][nt][1] + b1) * ms0;
            float v10 = (acc[mt][nt][2] + b0) * ms1;
            float v11 = (acc[mt][nt][3] + b1) * ms1;
            if (OUT_MODE == 0) {
                *(float2*)&outf[(size_t)r0       * N + c] = make_float2(v00, v01);
                *(float2*)&outf[(size_t)(r0 + 8) * N + c] = make_float2(v10, v11);
            } else {
                const int rr[2] = {r0, r0 + 8};
                const float vv[2][2] = {{v00, v01}, {v10, v11}};
                #pragma unroll
                for (int i = 0; i < 2; i++)
                    #pragma unroll
                    for (int q = 0; q < 2; q++) {
                        size_t ad = ((size_t)(rr[i] >> 12) << 22)
                                  + (size_t)(c + q) * 4096 + (rr[i] & 4095);
                        bf16 h, l; bfsplit(vv[i][q], h, l);
                        oThi[ad] = h; oTlo[ad] = l;
                    }
            }
        }
    }
}

// ============================================================================
// Projection. z=0: Kp[bh][lk][d] (fp32 row-major).  z=1: VpT[bh][d][lk] (fp32).
// grid = (LK/128=2, B*H=64, 2); BM=128(lk), BN=64(d), warps 4x2.
// ============================================================================
__global__ __launch_bounds__(256) void proj_tc()
{
    const int m0 = blockIdx.x * 128;
    const int bh = blockIdx.y;
    const int b  = bh >> 4, h = bh & 15;
    const int z  = blockIdx.z;

    const bf16* Ah = g_Ehi + ((size_t)h * LKv + m0) * Sv;
    const bf16* Al = g_Elo + ((size_t)h * LKv + m0) * Sv;
    const size_t boff = (size_t)(b * Dv + h * HDv) * Sv;
    const bf16* Bh = (z ? g_Vt_hi : g_Kt_hi) + boff;
    const bf16* Bl = (z ? g_Vt_lo : g_Kt_lo) + boff;

    float acc[2][4][4];
    #pragma unroll
    for (int a = 0; a < 2; a++)
        #pragma unroll
        for (int c = 0; c < 4; c++)
            #pragma unroll
            for (int r = 0; r < 4; r++) acc[a][c][r] = 0.0f;

    gemm_core<64, 4, 2>(Ah, Al, Bh, Bl, Sv, acc);

    const int lane = threadIdx.x & 31, warp = threadIdx.x >> 5;
    const int wm = warp >> 1, wn = warp & 1;
    const int gid = lane >> 2, tig = lane & 3;

    if (z == 0) {
        float* out = g_Kp + (size_t)bh * LKv * HDv;
        #pragma unroll
        for (int mt = 0; mt < 2; mt++) {
            const int k0 = m0 + wm * 32 + mt * 16 + gid;
            #pragma unroll
            for (int nt = 0; nt < 4; nt++) {
                const int d = wn * 32 + nt * 8 + tig * 2;
                *(float2*)&out[(size_t)k0       * HDv + d] =
                    make_float2(acc[mt][nt][0], acc[mt][nt][1]);
                *(float2*)&out[(size_t)(k0 + 8) * HDv + d] =
                    make_float2(acc[mt][nt][2], acc[mt][nt][3]);
            }
        }
    } else {
        float* out = g_VpT + (size_t)bh * HDv * LKv;
        #pragma unroll
        for (int mt = 0; mt < 2; mt++) {
            const int k0 = m0 + wm * 32 + mt * 16 + gid;
            #pragma unroll
            for (int nt = 0; nt < 4; nt++) {
                const int d = wn * 32 + nt * 8 + tig * 2;
                out[(size_t)d       * LKv + k0]     = acc[mt][nt][0];
                out[(size_t)(d + 1) * LKv + k0]     = acc[mt][nt][1];
                out[(size_t)d       * LKv + k0 + 8] = acc[mt][nt][2];
                out[(size_t)(d + 1) * LKv + k0 + 8] = acc[mt][nt][3];
            }
        }
    }
}

// ============================================================================
// Prepass: fp32 -> bf16 hi/lo split (elementwise)
// ============================================================================
__global__ void split_k(const float* __restrict__ in, bf16* __restrict__ hi,
                        bf16* __restrict__ lo, int n4)
{
    int i = (blockIdx.x * blockDim.x + threadIdx.x);
    if (i >= n4) return;
    float4 v = *(const float4*)&in[i * 4];
    bf16 h0, l0, h1, l1, h2, l2, h3, l3;
    bfsplit(v.x, h0, l0); bfsplit(v.y, h1, l1);
    bfsplit(v.z, h2, l2); bfsplit(v.w, h3, l3);
    __nv_bfloat162* ph = (__nv_bfloat162*)&hi[i * 4];
    __nv_bfloat162* pl = (__nv_bfloat162*)&lo[i * 4];
    ph[0] = __halves2bfloat162(h0, h1); ph[1] = __halves2bfloat162(h2, h3);
    pl[0] = __halves2bfloat162(l0, l1); pl[1] = __halves2bfloat162(l2, l3);
}

// Prepass: W[K=1024][N=1024] -> Wt hi/lo [N][K]  (transpose + split)
__global__ void tsplit_k(const float* __restrict__ in, bf16* __restrict__ hi,
                         bf16* __restrict__ lo)
{
    __shared__ float ts[32][33];
    const int bx = blockIdx.x * 32, by = blockIdx.y * 32;
    const int tx = threadIdx.x, ty = threadIdx.y;
    #pragma unroll
    for (int j = 0; j < 4; j++)
        ts[ty + j * 8][tx] = in[(size_t)(by + ty + j * 8) * Dv + bx + tx];
    __syncthreads();
    #pragma unroll
    for (int j = 0; j < 4; j++) {
        float v = ts[tx][ty + j * 8];
        bf16 h, l; bfsplit(v, h, l);
        size_t ad = (size_t)(bx + ty + j * 8) * Dv + by + tx;
        hi[ad] = h; lo[ad] = l;
    }
}

// ============================================================================
// Tensorized attention with online softmax (bf16x3 mma.sync).
// Block = 128 q-rows x (b,h). 8 warps; warp = 16 rows x all 256 lk.
// Kp/VpT consumed in two lk-chunks of 128, staged+split to smem in-kernel.
// Output: Xo bf16 hi/lo row-major (feeds final GEMM directly).
// smem 96KB: Qh 0 | Ql 16K | Kh 32K | Kl 48K | Vh 64K | Vl 80K.
// Xo f32 staging reuses [32K..64K) after the last chunk.
// ============================================================================
#define ATTN_SMEM 98304

__global__ __launch_bounds__(256) void attn_mma()
{
    extern __shared__ char smraw[];
    const unsigned sb = (unsigned)__cvta_generic_to_shared(smraw);

    const int t = threadIdx.x, lane = t & 31, warp = t >> 5;
    const int bh = blockIdx.y, b = bh >> 4, h = bh & 15;
    const int q0 = blockIdx.x * 128;

    const float* Qg  = g_Q   + ((size_t)(b * Sv + q0)) * Dv + h * HDv;
    const float* Kpg = g_Kp  + (size_t)bh * LKv * HDv;   // [lk][64]
    const float* Vtg = g_VpT + (size_t)bh * HDv * LKv;   // [d][256]

    const unsigned QH = 0, QL = 16384, KH = 32768, KL = 49152, VH = 65536, VL = 81920;

    // ---- stage Q (f32 -> hi/lo, 128B rows, chunk^(row&7) swizzle) ----
    #pragma unroll
    for (int r = 0; r < 8; r++) {
        int i = (t + r * 256) * 4;
        int row = i >> 6, d0 = i & 63;
        float4 v = *(const float4*)&Qg[(size_t)row * Dv + d0];
        unsigned off = (unsigned)row * 128 + ((unsigned)((d0 >> 3) ^ (row & 7))) * 16 + (d0 & 4) * 2;
        bf16 h0,l0,h1,l1,h2,l2,h3,l3;
        bfsplit(v.x,h0,l0); bfsplit(v.y,h1,l1); bfsplit(v.z,h2,l2); bfsplit(v.w,h3,l3);
        *(uint2*)(smraw + QH + off) = make_uint2(pack2(h0,h1), pack2(h2,h3));
        *(uint2*)(smraw + QL + off) = make_uint2(pack2(l0,l1), pack2(l2,l3));
    }

    const int gid = lane >> 2, tig = lane & 3;
    const int lr  = lane & 7;
    const int aLR = lr + ((lane >> 3) & 1) * 8;
    const int aLC = lane >> 4;
    const int jj  = lane >> 3;
    const int bLR = ((jj >> 1) & 1) * 8 + lr;
    const int bLC = jj & 1;
    const int m_w = warp * 16;
    const int rowA = m_w + aLR;

    float avacc[8][4];
    #pragma unroll
    for (int nt = 0; nt < 8; nt++)
        #pragma unroll
        for (int r = 0; r < 4; r++) avacc[nt][r] = 0.0f;
    float m0r = -1e30f, m1r = -1e30f, sum0 = 0.0f, sum1 = 0.0f;

    for (int c = 0; c < 2; c++) {
        // ---- stage Kp chunk [128 lk][64 d] and VpT chunk [64 d][128 lk] ----
        #pragma unroll
        for (int r = 0; r < 8; r++) {
            int i = (t + r * 256) * 4;
            {
                int row = i >> 6, d0 = i & 63;
                float4 v = *(const float4*)&Kpg[(size_t)(c * 128 + row) * HDv + d0];
                unsigned off = (unsigned)row * 128 + ((unsigned)((d0 >> 3) ^ (row & 7))) * 16 + (d0 & 4) * 2;
                bf16 h0,l0,h1,l1,h2,l2,h3,l3;
                bfsplit(v.x,h0,l0); bfsplit(v.y,h1,l1); bfsplit(v.z,h2,l2); bfsplit(v.w,h3,l3);
                *(uint2*)(smraw + KH + off) = make_uint2(pack2(h0,h1), pack2(h2,h3));
                *(uint2*)(smraw + KL + off) = make_uint2(pack2(l0,l1), pack2(l2,l3));
            }
            {
                int row = i >> 7, lk0 = i & 127;
                float4 v = *(const float4*)&Vtg[(size_t)row * LKv + c * 128 + lk0];
                unsigned off = (unsigned)row * 256 + ((unsigned)((lk0 >> 3) ^ (row & 7))) * 16 + (lk0 & 4) * 2;
                bf16 h0,l0,h1,l1,h2,l2,h3,l3;
                bfsplit(v.x,h0,l0); bfsplit(v.y,h1,l1); bfsplit(v.z,h2,l2); bfsplit(v.w,h3,l3);
                *(uint2*)(smraw + VH + off) = make_uint2(pack2(h0,h1), pack2(h2,h3));
                *(uint2*)(smraw + VL + off) = make_uint2(pack2(l0,l1), pack2(l2,l3));
            }
        }
        __syncthreads();

        // ---- scores S[16 x 128] = Q . Kp^T (bf16x3) ----
        float sacc[16][4];
        #pragma unroll
        for (int nt = 0; nt < 16; nt++)
            #pragma unroll
            for (int r = 0; r < 4; r++) sacc[nt][r] = 0.0f;

        #pragma unroll
        for (int ks = 0; ks < 4; ks++) {
            unsigned qh[4], ql[4];
            unsigned aoff = (unsigned)rowA * 128 + ((unsigned)((2*ks + aLC) ^ (rowA & 7))) * 16;
            ldsm4(qh[0], qh[1], qh[2], qh[3], sb + QH + aoff);
            ldsm4(ql[0], ql[1], ql[2], ql[3], sb + QL + aoff);
            #pragma unroll
            for (int p = 0; p < 8; p++) {
                int rB = p * 16 + bLR;
                unsigned boff = (unsigned)rB * 128 + ((unsigned)((2*ks + bLC) ^ (rB & 7))) * 16;
                unsigned kh[4], kl[4];
                ldsm4(kh[0], kh[1], kh[2], kh[3], sb + KH + boff);
                ldsm4(kl[0], kl[1], kl[2], kl[3], sb + KL + boff);
                mma_bf16(sacc[2*p],     qh, &kh[0]);
                mma_bf16(sacc[2*p],     qh, &kl[0]);
                mma_bf16(sacc[2*p],     ql, &kh[0]);
                mma_bf16(sacc[2*p+1],   qh, &kh[2]);
                mma_bf16(sacc[2*p+1],   qh, &kl[2]);
                mma_bf16(sacc[2*p+1],   ql, &kh[2]);
            }
        }

        // ---- online softmax update (rows gid / gid+8; cols spread over quad) ----
        float mc0 = -1e30f, mc1 = -1e30f;
        #pragma unroll
        for (int nt = 0; nt < 16; nt++) {
            mc0 = fmaxf(mc0, fmaxf(sacc[nt][0], sacc[nt][1]));
            mc1 = fmaxf(mc1, fmaxf(sacc[nt][2], sacc[nt][3]));
        }
        mc0 *= 0.125f; mc1 *= 0.125f;
        mc0 = fmaxf(mc0, __shfl_xor_sync(0xffffffffu, mc0, 1));
        mc0 = fmaxf(mc0, __shfl_xor_sync(0xffffffffu, mc0, 2));
        mc1 = fmaxf(mc1, __shfl_xor_sync(0xffffffffu, mc1, 1));
        mc1 = fmaxf(mc1, __shfl_xor_sync(0xffffffffu, mc1, 2));
        const float mn0 = fmaxf(m0r, mc0), mn1 = fmaxf(m1r, mc1);
        const float sc0 = __expf(m0r - mn0), sc1 = __expf(m1r - mn1);
        m0r = mn0; m1r = mn1;

        float rs0 = 0.0f, rs1 = 0.0f;
        #pragma unroll
        for (int nt = 0; nt < 16; nt++) {
            float p0 = __expf(0.125f * sacc[nt][0] - mn0);
            float p1 = __expf(0.125f * sacc[nt][1] - mn0);
            float p2 = __expf(0.125f * sacc[nt][2] - mn1);
            float p3 = __expf(0.125f * sacc[nt][3] - mn1);
            sacc[nt][0] = p0; sacc[nt][1] = p1; sacc[nt][2] = p2; sacc[nt][3] = p3;
            rs0 += p0 + p1; rs1 += p2 + p3;
        }
        rs0 += __shfl_xor_sync(0xffffffffu, rs0, 1);
        rs0 += __shfl_xor_sync(0xffffffffu, rs0, 2);
        rs1 += __shfl_xor_sync(0xffffffffu, rs1, 1);
        rs1 += __shfl_xor_sync(0xffffffffu, rs1, 2);
        sum0 = sum0 * sc0 + rs0;
        sum1 = sum1 * sc1 + rs1;
        #pragma unroll
        for (int nt = 0; nt < 8; nt++) {
            avacc[nt][0] *= sc0; avacc[nt][1] *= sc0;
            avacc[nt][2] *= sc1; avacc[nt][3] *= sc1;
        }

        // ---- AV: Xo += P . VpT^T (bf16x3; P regs reused as A-fragments) ----
        #pragma unroll
        for (int kt = 0; kt < 8; kt++) {
            bf16 hh[8], ll[8];
            bfsplit(sacc[2*kt][0],   hh[0], ll[0]);
            bfsplit(sacc[2*kt][1],   hh[1], ll[1]);
            bfsplit(sacc[2*kt][2],   hh[2], ll[2]);
            bfsplit(sacc[2*kt][3],   hh[3], ll[3]);
            bfsplit(sacc[2*kt+1][0], hh[4], ll[4]);
            bfsplit(sacc[2*kt+1][1], hh[5], ll[5]);
            bfsplit(sacc[2*kt+1][2], hh[6], ll[6]);
            bfsplit(sacc[2*kt+1][3], hh[7], ll[7]);
            unsigned ah[4] = {pack2(hh[0],hh[1]), pack2(hh[2],hh[3]),
                              pack2(hh[4],hh[5]), pack2(hh[6],hh[7])};
            unsigned al[4] = {pack2(ll[0],ll[1]), pack2(ll[2],ll[3]),
                              pack2(ll[4],ll[5]), pack2(ll[6],ll[7])};
            #pragma unroll
            for (int p = 0; p < 4; p++) {
                int rB = p * 16 + bLR;
                unsigned boff = (unsigned)rB * 256 + ((unsigned)((2*kt + bLC) ^ (rB & 7))) * 16;
                unsigned vh[4], vl[4];
                ldsm4(vh[0], vh[1], vh[2], vh[3], sb + VH + boff);
                ldsm4(vl[0], vl[1], vl[2], vl[3], sb + VL + boff);
                mma_bf16(avacc[2*p],   ah, &vh[0]);
                mma_bf16(avacc[2*p],   ah, &vl[0]);
                mma_bf16(avacc[2*p],   al, &vh[0]);
                mma_bf16(avacc[2*p+1], ah, &vh[2]);
                mma_bf16(avacc[2*p+1], ah, &vl[2]);
                mma_bf16(avacc[2*p+1], al, &vh[2]);
            }
        }
        __syncthreads();   // all reads of K/V chunk done before restage/reuse
    }

    // ---- finalize: divide by sum, stage through smem, split-store ----
    const float i0 = 1.0f / sum0, i1 = 1.0f / sum1;
    float* Xs = (float*)(smraw + 32768);   // [128][64] fp32 (reuses K region)
    #pragma unroll
    for (int nt = 0; nt < 8; nt++) {
        const int col = 8 * nt + 2 * tig;
        Xs[(m_w + gid)     * 64 + col]     = avacc[nt][0] * i0;
        Xs[(m_w + gid)     * 64 + col + 1] = avacc[nt][1] * i0;
        Xs[(m_w + gid + 8) * 64 + col]     = avacc[nt][2] * i1;
        Xs[(m_w + gid + 8) * 64 + col + 1] = avacc[nt][3] * i1;
    }
    __syncthreads();

    #pragma unroll
    for (int r = 0; r < 8; r++) {
        int i = (t + r * 256) * 4;
        int row = i >> 6, d0 = i & 63;
        float4 v = *(const float4*)&Xs[row * 64 + d0];
        bf16 h0,l0,h1,l1,h2,l2,h3,l3;
        bfsplit(v.x,h0,l0); bfsplit(v.y,h1,l1); bfsplit(v.z,h2,l2); bfsplit(v.w,h3,l3);
        size_t ad = ((size_t)(b * Sv + q0 + row)) * Dv + h * HDv + d0;
        *(uint2*)&g_XoHi[ad] = make_uint2(pack2(h0,h1), pack2(h2,h3));
        *(uint2*)&g_XoLo[ad] = make_uint2(pack2(l0,l1), pack2(l2,l3));
    }
}

// ============================================================================
extern "C" void kernel_launch(void* const* d_in, const int* in_sizes, int n_in,
                              void* d_out, int out_size)
{
    const float* X    = (const float*)d_in[0];
    const float* mask = (const float*)d_in[1];
    const float* Wq   = (const float*)d_in[2];
    const float* bq   = (const float*)d_in[3];
    const float* Wk   = (const float*)d_in[4];
    const float* bk   = (const float*)d_in[5];
    const float* Wv   = (const float*)d_in[6];
    const float* bv   = (const float*)d_in[7];
    const float* E    = (const float*)d_in[8];
    const float* Wo   = (const float*)d_in[9];
    const float* bo   = (const float*)d_in[10];
    float* out        = (float*)d_out;

    bf16 *xhi, *xlo, *ehi, *elo, *wth, *wtl, *kth, *ktl, *vth, *vtl, *xoh, *xol;
    float *gQ;
    cudaGetSymbolAddress((void**)&xhi, g_Xhi);  cudaGetSymbolAddress((void**)&xlo, g_Xlo);
    cudaGetSymbolAddress((void**)&ehi, g_Ehi);  cudaGetSymbolAddress((void**)&elo, g_Elo);
    cudaGetSymbolAddress((void**)&wth, g_Wt_hi);cudaGetSymbolAddress((void**)&wtl, g_Wt_lo);
    cudaGetSymbolAddress((void**)&kth, g_Kt_hi);cudaGetSymbolAddress((void**)&ktl, g_Kt_lo);
    cudaGetSymbolAddress((void**)&vth, g_Vt_hi);cudaGetSymbolAddress((void**)&vtl, g_Vt_lo);
    cudaGetSymbolAddress((void**)&xoh, g_XoHi); cudaGetSymbolAddress((void**)&xol, g_XoLo);
    cudaGetSymbolAddress((void**)&gQ,  g_Q);

    const long long WSZ = (long long)Dv * Dv;

    cudaFuncSetAttribute(gemm_main<0>, cudaFuncAttributeMaxDynamicSharedMemorySize, 65536);
    cudaFuncSetAttribute(gemm_main<1>, cudaFuncAttributeMaxDynamicSharedMemorySize, 65536);
    cudaFuncSetAttribute(proj_tc,      cudaFuncAttributeMaxDynamicSharedMemorySize, 49152);
    cudaFuncSetAttribute(attn_mma,     cudaFuncAttributeMaxDynamicSharedMemorySize, ATTN_SMEM);

    // -------- prepass: splits + weight transposes --------
    split_k<<<(int)(NELEM/4/256), 256>>>(X, xhi, xlo, (int)(NELEM/4));
    split_k<<<(int)(NELEM/4/256), 256>>>(E, ehi, elo, (int)(NELEM/4));
    tsplit_k<<<dim3(32,32), dim3(32,8)>>>(Wq, wth + 0*WSZ, wtl + 0*WSZ);
    tsplit_k<<<dim3(32,32), dim3(32,8)>>>(Wk, wth + 1*WSZ, wtl + 1*WSZ);
    tsplit_k<<<dim3(32,32), dim3(32,8)>>>(Wv, wth + 2*WSZ, wtl + 2*WSZ);
    tsplit_k<<<dim3(32,32), dim3(32,8)>>>(Wo, wth + 3*WSZ, wtl + 3*WSZ);

    dim3 gg(Dv / 128, Mrows / 128);   // (8, 128)

    // -------- QKV projections --------
    gemm_main<0><<<gg, 256, 65536>>>(xhi, xlo, wth + 0*WSZ, wtl + 0*WSZ,
                                     bq, nullptr, gQ, nullptr, nullptr, Dv, Dv);
    gemm_main<1><<<gg, 256, 65536>>>(xhi, xlo, wth + 1*WSZ, wtl + 1*WSZ,
                                     bk, mask, nullptr, kth, ktl, Dv, Dv);
    gemm_main<1><<<gg, 256, 65536>>>(xhi, xlo, wth + 2*WSZ, wtl + 2*WSZ,
                                     bv, mask, nullptr, vth, vtl, Dv, Dv);

    // -------- Kp / VpT = E @ (K*m), (E @ (V*m))^T --------
    proj_tc<<<dim3(LKv/128, Bv*Hv, 2), 256, 49152>>>();

    // -------- tensorized attention -> XoHi/XoLo --------
    attn_mma<<<dim3(Sv/128, Bv*Hv), 256, ATTN_SMEM>>>();

    // -------- output projection -> d_out --------
    gemm_main<0><<<gg, 256, 65536>>>(xoh, xol, wth + 3*WSZ, wtl + 3*WSZ,
                                     bo, nullptr, out, nullptr, nullptr, Dv, Dv);
}

// round 8
// speedup vs baseline: 3.2084x; 1.0907x over previous
#include <cuda_runtime.h>
#include <cuda_bf16.h>
#include <math.h>
#include <stdint.h>

// Problem constants
#define Bv   4
#define Sv   4096
#define Dv   1024
#define Hv   16
#define HDv  64
#define LKv  256
#define Mrows (Bv*Sv)                       // 16384
#define NELEM ((long long)Mrows * Dv)       // 16777216

typedef __nv_bfloat16 bf16;

// ---------------- scratch (static device globals; no allocation allowed) ----
__device__ bf16 g_Xhi[NELEM],  g_Xlo[NELEM];    // X split
__device__ bf16 g_Ehi[NELEM],  g_Elo[NELEM];    // E split
__device__ bf16 g_Wt_hi[4][(long long)Dv*Dv];   // Wq,Wk,Wv,Wo transposed [n][k] (contiguous!)
__device__ bf16 g_Wt_lo[4][(long long)Dv*Dv];
__device__ bf16 g_Kt_hi[NELEM], g_Kt_lo[NELEM]; // K^T [b][d_global][s], masked
__device__ bf16 g_Vt_hi[NELEM], g_Vt_lo[NELEM];
__device__ bf16 g_XoHi[NELEM],  g_XoLo[NELEM];  // attn output split (row-major)
__device__ float g_Q [NELEM];                   // fp32 Q (row-major)
__device__ float g_Kp [(long long)Bv*Hv*LKv*HDv];  // Kp [bh][lk][d]
__device__ float g_VpT[(long long)Bv*Hv*HDv*LKv];  // Vp^T [bh][d][lk]
__device__ float g_bias3[3 * Dv];               // packed [bq|bk|bv]

// ---------------- helpers ----------------------------------------------------
__device__ __forceinline__ void bfsplit(float v, bf16& h, bf16& l) {
    h = __float2bfloat16(v);
    l = __float2bfloat16(v - __bfloat162float(h));
}
__device__ __forceinline__ unsigned pack2(bf16 a, bf16 b) {
    __nv_bfloat162 t = __halves2bfloat162(a, b);
    return *reinterpret_cast<unsigned*>(&t);
}

// D += A(16x16,row) * B(16x8,col)   (bf16 in, fp32 acc)
__device__ __forceinline__ void mma_bf16(float* d, const unsigned* a,
                                         const unsigned* b) {
    asm volatile(
        "mma.sync.aligned.m16n8k16.row.col.f32.bf16.bf16.f32 "
        "{%0,%1,%2,%3}, {%4,%5,%6,%7}, {%8,%9}, {%0,%1,%2,%3};\n"
        : "+f"(d[0]), "+f"(d[1]), "+f"(d[2]), "+f"(d[3])
        : "r"(a[0]), "r"(a[1]), "r"(a[2]), "r"(a[3]),
          "r"(b[0]), "r"(b[1]));
}

__device__ __forceinline__ void ldsm4(unsigned& r0, unsigned& r1,
                                      unsigned& r2, unsigned& r3, unsigned addr) {
    asm volatile("ldmatrix.sync.aligned.m8n8.x4.shared.b16 {%0,%1,%2,%3}, [%4];\n"
                 : "=r"(r0), "=r"(r1), "=r"(r2), "=r"(r3) : "r"(addr));
}

__device__ __forceinline__ void cp16(unsigned dst, const void* src) {
    asm volatile("cp.async.cg.shared.global [%0], [%1], 16;\n" :: "r"(dst), "l"(src));
}
__device__ __forceinline__ void cp_commit() { asm volatile("cp.async.commit_group;\n"); }
__device__ __forceinline__ void cp_wait1()  { asm volatile("cp.async.wait_group 1;\n"); }
__device__ __forceinline__ void cp_wait0()  { asm volatile("cp.async.wait_group 0;\n"); }

// swizzle for 64B rows: chunk' = chunk ^ ((row>>1)&3), in 16B units
__device__ __forceinline__ unsigned swz16(int row, int chunk) {
    return (unsigned)(row * 4 + (chunk ^ ((row >> 1) & 3)));
}

// ============================================================================
// GEMM core (mma.sync): C[128xBN] += (Ahi+Alo)[128,K]*(Bhi+Blo)[BN,K]^T
// bf16x3. BK=32, 3-stage cp.async pipeline, ONE __syncthreads per k-tile.
// ============================================================================
template<int BN, int WR, int WC>
__device__ __forceinline__ void gemm_core(
    const bf16* __restrict__ Ahg, const bf16* __restrict__ Alg,
    const bf16* __restrict__ Bhg, const bf16* __restrict__ Blg,
    int K,
    float (&acc)[(128/WR)/16][(BN/WC)/8][4])
{
    constexpr int BM = 128, BK = 32;
    constexpr int MT = (BM/WR)/16;
    constexpr int NT = (BN/WC)/8;
    constexpr int A_ELE = BM*BK, B_ELE = BN*BK;
    constexpr unsigned OF_AL = A_ELE*2;
    constexpr unsigned OF_BH = 2*A_ELE*2;
    constexpr unsigned OF_BL = (2*A_ELE+B_ELE)*2;
    constexpr unsigned STAGE_B = (2*A_ELE+2*B_ELE)*2;

    extern __shared__ bf16 smem_dyn[];
    const unsigned s0 = (unsigned)__cvta_generic_to_shared(smem_dyn);

    const int t = threadIdx.x, lane = t & 31, warp = t >> 5;
    const int wm = warp / WC, wn = warp % WC;
    const int m_w = wm * (BM/WR), n_w = wn * (BN/WC);

    const int a_row = t >> 1;
    const int a_c0  = (t & 1) * 2;
    const unsigned a_d0 = swz16(a_row, a_c0)     * 16;
    const unsigned a_d1 = swz16(a_row, a_c0 + 1) * 16;

    int b_row, b_c0;
    if (BN == 128) { b_row = t >> 1; b_c0 = (t & 1) * 2; }
    else           { b_row = t >> 2; b_c0 = t & 3; }
    const unsigned b_d0 = swz16(b_row, b_c0) * 16;
    const unsigned b_d1 = (BN == 128) ? swz16(b_row, b_c0 + 1) * 16 : 0;

    auto issue = [&](int st, int k0) {
        const unsigned sb = s0 + (unsigned)st * STAGE_B;
        const char* pah = (const char*)(Ahg + (size_t)a_row * K + k0);
        const char* pal = (const char*)(Alg + (size_t)a_row * K + k0);
        cp16(sb + a_d0,         pah + a_c0*16);
        cp16(sb + a_d1,         pah + a_c0*16 + 16);
        cp16(sb + OF_AL + a_d0, pal + a_c0*16);
        cp16(sb + OF_AL + a_d1, pal + a_c0*16 + 16);
        const char* pbh = (const char*)(Bhg + (size_t)b_row * K + k0);
        const char* pbl = (const char*)(Blg + (size_t)b_row * K + k0);
        cp16(sb + OF_BH + b_d0, pbh + b_c0*16);
        cp16(sb + OF_BL + b_d0, pbl + b_c0*16);
        if (BN == 128) {
            cp16(sb + OF_BH + b_d1, pbh + b_c0*16 + 16);
            cp16(sb + OF_BL + b_d1, pbl + b_c0*16 + 16);
        }
    };

    const int lr  = lane & 7;
    const int aLR = lr + ((lane >> 3) & 1) * 8;
    const int aLC = lane >> 4;
    unsigned adA[MT][2];
    #pragma unroll
    for (int mt = 0; mt < MT; mt++)
        #pragma unroll
        for (int ks = 0; ks < 2; ks++) {
            int row = m_w + mt*16 + aLR;
            adA[mt][ks] = swz16(row, 2*ks + aLC) * 16;
        }
    const int j   = lane >> 3;
    const int bLR = ((j >> 1) & 1) * 8 + lr;
    const int bLC = j & 1;
    unsigned adB[NT/2][2];
    #pragma unroll
    for (int p = 0; p < NT/2; p++)
        #pragma unroll
        for (int ks = 0; ks < 2; ks++) {
            int row = n_w + p*16 + bLR;
            adB[p][ks] = swz16(row, 2*ks + bLC) * 16;
        }

    const int ntiles = K / BK;
    issue(0, 0); cp_commit();
    if (ntiles > 1) { issue(1, BK); cp_commit(); }

    for (int i = 0; i < ntiles; i++) {
        if (i + 1 < ntiles) cp_wait1(); else cp_wait0();
        __syncthreads();                       // tile i ready; stage (i+2)%3 free
        if (i + 2 < ntiles) { issue((i + 2) % 3, (i + 2) * BK); cp_commit(); }

        const unsigned sb = s0 + (unsigned)(i % 3) * STAGE_B;
        #pragma unroll
        for (int ks = 0; ks < 2; ks++) {
            unsigned bh[NT][2], bl[NT][2];
            #pragma unroll
            for (int p = 0; p < NT/2; p++) {
                ldsm4(bh[2*p][0], bh[2*p][1], bh[2*p+1][0], bh[2*p+1][1],
                      sb + OF_BH + adB[p][ks]);
                ldsm4(bl[2*p][0], bl[2*p][1], bl[2*p+1][0], bl[2*p+1][1],
                      sb + OF_BL + adB[p][ks]);
            }
            #pragma unroll
            for (int mt = 0; mt < MT; mt++) {
                unsigned ah[4], al[4];
                ldsm4(ah[0], ah[1], ah[2], ah[3], sb + adA[mt][ks]);
                ldsm4(al[0], al[1], al[2], al[3], sb + OF_AL + adA[mt][ks]);
                #pragma unroll
                for (int nt = 0; nt < NT; nt++) {
                    mma_bf16(acc[mt][nt], ah, bh[nt]);
                    mma_bf16(acc[mt][nt], ah, bl[nt]);
                    mma_bf16(acc[mt][nt], al, bh[nt]);
                }
            }
        }
    }
}

// ============================================================================
// Fused QKV GEMM: A = X split, B = [Wq^T|Wk^T|Wv^T] rows (N=3072), K=1024.
// n<1024: Q -> fp32 g_Q. n in [1024,2048): K -> masked split-transposed Kt.
// n >= 2048: V -> masked split-transposed Vt.
// grid = (24, 128), 256 threads.
// ============================================================================
__global__ __launch_bounds__(256) void gemm_qkv(
    const bf16* __restrict__ Ahi, const bf16* __restrict__ Alo,
    const bf16* __restrict__ Bhi, const bf16* __restrict__ Blo,
    const float* __restrict__ mask)
{
    const int m0 = blockIdx.y * 128, n0 = blockIdx.x * 128;
    float acc[4][4][4];
    #pragma unroll
    for (int a = 0; a < 4; a++)
        #pragma unroll
        for (int b = 0; b < 4; b++)
            #pragma unroll
            for (int c = 0; c < 4; c++) acc[a][b][c] = 0.0f;

    gemm_core<128, 2, 4>(Ahi + (size_t)m0 * Dv, Alo + (size_t)m0 * Dv,
                         Bhi + (size_t)n0 * Dv, Blo + (size_t)n0 * Dv, Dv, acc);

    const int lane = threadIdx.x & 31, warp = threadIdx.x >> 5;
    const int wm = warp >> 2, wn = warp & 3;
    const int gid = lane >> 2, tig = lane & 3;

    const bool isQ = (n0 < Dv);
    const bool isV = (n0 >= 2 * Dv);
    bf16* oh = isV ? g_Vt_hi : g_Kt_hi;
    bf16* ol = isV ? g_Vt_lo : g_Kt_lo;
    const int dbase = isQ ? 0 : (isV ? 2 * Dv : Dv);

    #pragma unroll
    for (int mt = 0; mt < 4; mt++) {
        const int r0 = m0 + wm * 64 + mt * 16 + gid;
        const float ms0 = isQ ? 1.0f : mask[r0];
        const float ms1 = isQ ? 1.0f : mask[r0 + 8];
        #pragma unroll
        for (int nt = 0; nt < 4; nt++) {
            const int c = n0 + wn * 32 + nt * 8 + tig * 2;
            const float b0 = g_bias3[c], b1 = g_bias3[c + 1];
            float v00 = (acc[mt][nt][0] + b0) * ms0;
            float v01 = (acc[mt][nt][1] + b1) * ms0;
            float v10 = (acc[mt][nt][2] + b0) * ms1;
            float v11 = (acc[mt][nt][3] + b1) * ms1;
            if (isQ) {
                *(float2*)&g_Q[(size_t)r0       * Dv + c] = make_float2(v00, v01);
                *(float2*)&g_Q[(size_t)(r0 + 8) * Dv + c] = make_float2(v10, v11);
            } else {
                const int rr[2] = {r0, r0 + 8};
                const float vv[2][2] = {{v00, v01}, {v10, v11}};
                #pragma unroll
                for (int i = 0; i < 2; i++)
                    #pragma unroll
                    for (int q = 0; q < 2; q++) {
                        size_t ad = ((size_t)(rr[i] >> 12) << 22)
                                  + (size_t)(c - dbase + q) * 4096 + (rr[i] & 4095);
                        bf16 h, l; bfsplit(vv[i][q], h, l);
                        oh[ad] = h; ol[ad] = l;
                    }
            }
        }
    }
}

// ============================================================================
// Output GEMM: out = Xo @ Wo + bo (fp32 out).  grid = (8, 128).
// ============================================================================
__global__ __launch_bounds__(256) void gemm_out(
    const bf16* __restrict__ Ahi, const bf16* __restrict__ Alo,
    const bf16* __restrict__ Bhi, const bf16* __restrict__ Blo,
    const float* __restrict__ bias, float* __restrict__ outf)
{
    const int m0 = blockIdx.y * 128, n0 = blockIdx.x * 128;
    float acc[4][4][4];
    #pragma unroll
    for (int a = 0; a < 4; a++)
        #pragma unroll
        for (int b = 0; b < 4; b++)
            #pragma unroll
            for (int c = 0; c < 4; c++) acc[a][b][c] = 0.0f;

    gemm_core<128, 2, 4>(Ahi + (size_t)m0 * Dv, Alo + (size_t)m0 * Dv,
                         Bhi + (size_t)n0 * Dv, Blo + (size_t)n0 * Dv, Dv, acc);

    const int lane = threadIdx.x & 31, warp = threadIdx.x >> 5;
    const int wm = warp >> 2, wn = warp & 3;
    const int gid = lane >> 2, tig = lane & 3;

    #pragma unroll
    for (int mt = 0; mt < 4; mt++) {
        const int r0 = m0 + wm * 64 + mt * 16 + gid;
        #pragma unroll
        for (int nt = 0; nt < 4; nt++) {
            const int c = n0 + wn * 32 + nt * 8 + tig * 2;
            const float b0 = bias[c], b1 = bias[c + 1];
            *(float2*)&outf[(size_t)r0       * Dv + c] =
                make_float2(acc[mt][nt][0] + b0, acc[mt][nt][1] + b1);
            *(float2*)&outf[(size_t)(r0 + 8) * Dv + c] =
                make_float2(acc[mt][nt][2] + b0, acc[mt][nt][3] + b1);
        }
    }
}

// ============================================================================
// Projection. z=0: Kp[bh][lk][d] (fp32 row-major).  z=1: VpT[bh][d][lk] (fp32).
// grid = (LK/128=2, B*H=64, 2); BM=128(lk), BN=64(d), warps 4x2.
// ============================================================================
__global__ __launch_bounds__(256) void proj_tc()
{
    const int m0 = blockIdx.x * 128;
    const int bh = blockIdx.y;
    const int b  = bh >> 4, h = bh & 15;
    const int z  = blockIdx.z;

    const bf16* Ah = g_Ehi + ((size_t)h * LKv + m0) * Sv;
    const bf16* Al = g_Elo + ((size_t)h * LKv + m0) * Sv;
    const size_t boff = (size_t)(b * Dv + h * HDv) * Sv;
    const bf16* Bh = (z ? g_Vt_hi : g_Kt_hi) + boff;
    const bf16* Bl = (z ? g_Vt_lo : g_Kt_lo) + boff;

    float acc[2][4][4];
    #pragma unroll
    for (int a = 0; a < 2; a++)
        #pragma unroll
        for (int c = 0; c < 4; c++)
            #pragma unroll
            for (int r = 0; r < 4; r++) acc[a][c][r] = 0.0f;

    gemm_core<64, 4, 2>(Ah, Al, Bh, Bl, Sv, acc);

    const int lane = threadIdx.x & 31, warp = threadIdx.x >> 5;
    const int wm = warp >> 1, wn = warp & 1;
    const int gid = lane >> 2, tig = lane & 3;

    if (z == 0) {
        float* out = g_Kp + (size_t)bh * LKv * HDv;
        #pragma unroll
        for (int mt = 0; mt < 2; mt++) {
            const int k0 = m0 + wm * 32 + mt * 16 + gid;
            #pragma unroll
            for (int nt = 0; nt < 4; nt++) {
                const int d = wn * 32 + nt * 8 + tig * 2;
                *(float2*)&out[(size_t)k0       * HDv + d] =
                    make_float2(acc[mt][nt][0], acc[mt][nt][1]);
                *(float2*)&out[(size_t)(k0 + 8) * HDv + d] =
                    make_float2(acc[mt][nt][2], acc[mt][nt][3]);
            }
        }
    } else {
        float* out = g_VpT + (size_t)bh * HDv * LKv;
        #pragma unroll
        for (int mt = 0; mt < 2; mt++) {
            const int k0 = m0 + wm * 32 + mt * 16 + gid;
            #pragma unroll
            for (int nt = 0; nt < 4; nt++) {
                const int d = wn * 32 + nt * 8 + tig * 2;
                out[(size_t)d       * LKv + k0]     = acc[mt][nt][0];
                out[(size_t)(d + 1) * LKv + k0]     = acc[mt][nt][1];
                out[(size_t)d       * LKv + k0 + 8] = acc[mt][nt][2];
                out[(size_t)(d + 1) * LKv + k0 + 8] = acc[mt][nt][3];
            }
        }
    }
}

// ============================================================================
// Prepass kernels
// ============================================================================
__global__ void split_k(const float* __restrict__ in, bf16* __restrict__ hi,
                        bf16* __restrict__ lo, int n4)
{
    int i = (blockIdx.x * blockDim.x + threadIdx.x);
    if (i >= n4) return;
    float4 v = *(const float4*)&in[i * 4];
    bf16 h0, l0, h1, l1, h2, l2, h3, l3;
    bfsplit(v.x, h0, l0); bfsplit(v.y, h1, l1);
    bfsplit(v.z, h2, l2); bfsplit(v.w, h3, l3);
    __nv_bfloat162* ph = (__nv_bfloat162*)&hi[i * 4];
    __nv_bfloat162* pl = (__nv_bfloat162*)&lo[i * 4];
    ph[0] = __halves2bfloat162(h0, h1); ph[1] = __halves2bfloat162(h2, h3);
    pl[0] = __halves2bfloat162(l0, l1); pl[1] = __halves2bfloat162(l2, l3);
}

__global__ void tsplit_k(const float* __restrict__ in, bf16* __restrict__ hi,
                         bf16* __restrict__ lo)
{
    __shared__ float ts[32][33];
    const int bx = blockIdx.x * 32, by = blockIdx.y * 32;
    const int tx = threadIdx.x, ty = threadIdx.y;
    #pragma unroll
    for (int j = 0; j < 4; j++)
        ts[ty + j * 8][tx] = in[(size_t)(by + ty + j * 8) * Dv + bx + tx];
    __syncthreads();
    #pragma unroll
    for (int j = 0; j < 4; j++) {
        float v = ts[tx][ty + j * 8];
        bf16 h, l; bfsplit(v, h, l);
        size_t ad = (size_t)(bx + ty + j * 8) * Dv + by + tx;
        hi[ad] = h; lo[ad] = l;
    }
}

__global__ void pack_bias(const float* __restrict__ bq, const float* __restrict__ bk,
                          const float* __restrict__ bv)
{
    int i = blockIdx.x * blockDim.x + threadIdx.x;
    if (i < Dv)            g_bias3[i] = bq[i];
    else if (i < 2 * Dv)   g_bias3[i] = bk[i - Dv];
    else if (i < 3 * Dv)   g_bias3[i] = bv[i - 2 * Dv];
}

// ============================================================================
// Tensorized attention with online softmax (bf16x3 mma.sync). (unchanged R7)
// ============================================================================
#define ATTN_SMEM 98304

__global__ __launch_bounds__(256) void attn_mma()
{
    extern __shared__ char smraw[];
    const unsigned sb = (unsigned)__cvta_generic_to_shared(smraw);

    const int t = threadIdx.x, lane = t & 31, warp = t >> 5;
    const int bh = blockIdx.y, b = bh >> 4, h = bh & 15;
    const int q0 = blockIdx.x * 128;

    const float* Qg  = g_Q   + ((size_t)(b * Sv + q0)) * Dv + h * HDv;
    const float* Kpg = g_Kp  + (size_t)bh * LKv * HDv;
    const float* Vtg = g_VpT + (size_t)bh * HDv * LKv;

    const unsigned QH = 0, QL = 16384, KH = 32768, KL = 49152, VH = 65536, VL = 81920;

    #pragma unroll
    for (int r = 0; r < 8; r++) {
        int i = (t + r * 256) * 4;
        int row = i >> 6, d0 = i & 63;
        float4 v = *(const float4*)&Qg[(size_t)row * Dv + d0];
        unsigned off = (unsigned)row * 128 + ((unsigned)((d0 >> 3) ^ (row & 7))) * 16 + (d0 & 4) * 2;
        bf16 h0,l0,h1,l1,h2,l2,h3,l3;
        bfsplit(v.x,h0,l0); bfsplit(v.y,h1,l1); bfsplit(v.z,h2,l2); bfsplit(v.w,h3,l3);
        *(uint2*)(smraw + QH + off) = make_uint2(pack2(h0,h1), pack2(h2,h3));
        *(uint2*)(smraw + QL + off) = make_uint2(pack2(l0,l1), pack2(l2,l3));
    }

    const int gid = lane >> 2, tig = lane & 3;
    const int lr  = lane & 7;
    const int aLR = lr + ((lane >> 3) & 1) * 8;
    const int aLC = lane >> 4;
    const int jj  = lane >> 3;
    const int bLR = ((jj >> 1) & 1) * 8 + lr;
    const int bLC = jj & 1;
    const int m_w = warp * 16;
    const int rowA = m_w + aLR;

    float avacc[8][4];
    #pragma unroll
    for (int nt = 0; nt < 8; nt++)
        #pragma unroll
        for (int r = 0; r < 4; r++) avacc[nt][r] = 0.0f;
    float m0r = -1e30f, m1r = -1e30f, sum0 = 0.0f, sum1 = 0.0f;

    for (int c = 0; c < 2; c++) {
        #pragma unroll
        for (int r = 0; r < 8; r++) {
            int i = (t + r * 256) * 4;
            {
                int row = i >> 6, d0 = i & 63;
                float4 v = *(const float4*)&Kpg[(size_t)(c * 128 + row) * HDv + d0];
                unsigned off = (unsigned)row * 128 + ((unsigned)((d0 >> 3) ^ (row & 7))) * 16 + (d0 & 4) * 2;
                bf16 h0,l0,h1,l1,h2,l2,h3,l3;
                bfsplit(v.x,h0,l0); bfsplit(v.y,h1,l1); bfsplit(v.z,h2,l2); bfsplit(v.w,h3,l3);
                *(uint2*)(smraw + KH + off) = make_uint2(pack2(h0,h1), pack2(h2,h3));
                *(uint2*)(smraw + KL + off) = make_uint2(pack2(l0,l1), pack2(l2,l3));
            }
            {
                int row = i >> 7, lk0 = i & 127;
                float4 v = *(const float4*)&Vtg[(size_t)row * LKv + c * 128 + lk0];
                unsigned off = (unsigned)row * 256 + ((unsigned)((lk0 >> 3) ^ (row & 7))) * 16 + (lk0 & 4) * 2;
                bf16 h0,l0,h1,l1,h2,l2,h3,l3;
                bfsplit(v.x,h0,l0); bfsplit(v.y,h1,l1); bfsplit(v.z,h2,l2); bfsplit(v.w,h3,l3);
                *(uint2*)(smraw + VH + off) = make_uint2(pack2(h0,h1), pack2(h2,h3));
                *(uint2*)(smraw + VL + off) = make_uint2(pack2(l0,l1), pack2(l2,l3));
            }
        }
        __syncthreads();

        float sacc[16][4];
        #pragma unroll
        for (int nt = 0; nt < 16; nt++)
            #pragma unroll
            for (int r = 0; r < 4; r++) sacc[nt][r] = 0.0f;

        #pragma unroll
        for (int ks = 0; ks < 4; ks++) {
            unsigned qh[4], ql[4];
            unsigned aoff = (unsigned)rowA * 128 + ((unsigned)((2*ks + aLC) ^ (rowA & 7))) * 16;
            ldsm4(qh[0], qh[1], qh[2], qh[3], sb + QH + aoff);
            ldsm4(ql[0], ql[1], ql[2], ql[3], sb + QL + aoff);
            #pragma unroll
            for (int p = 0; p < 8; p++) {
                int rB = p * 16 + bLR;
                unsigned boff = (unsigned)rB * 128 + ((unsigned)((2*ks + bLC) ^ (rB & 7))) * 16;
                unsigned kh[4], kl[4];
                ldsm4(kh[0], kh[1], kh[2], kh[3], sb + KH + boff);
                ldsm4(kl[0], kl[1], kl[2], kl[3], sb + KL + boff);
                mma_bf16(sacc[2*p],     qh, &kh[0]);
                mma_bf16(sacc[2*p],     qh, &kl[0]);
                mma_bf16(sacc[2*p],     ql, &kh[0]);
                mma_bf16(sacc[2*p+1],   qh, &kh[2]);
                mma_bf16(sacc[2*p+1],   qh, &kl[2]);
                mma_bf16(sacc[2*p+1],   ql, &kh[2]);
            }
        }

        float mc0 = -1e30f, mc1 = -1e30f;
        #pragma unroll
        for (int nt = 0; nt < 16; nt++) {
            mc0 = fmaxf(mc0, fmaxf(sacc[nt][0], sacc[nt][1]));
            mc1 = fmaxf(mc1, fmaxf(sacc[nt][2], sacc[nt][3]));
        }
        mc0 *= 0.125f; mc1 *= 0.125f;
        mc0 = fmaxf(mc0, __shfl_xor_sync(0xffffffffu, mc0, 1));
        mc0 = fmaxf(mc0, __shfl_xor_sync(0xffffffffu, mc0, 2));
        mc1 = fmaxf(mc1, __shfl_xor_sync(0xffffffffu, mc1, 1));
        mc1 = fmaxf(mc1, __shfl_xor_sync(0xffffffffu, mc1, 2));
        const float mn0 = fmaxf(m0r, mc0), mn1 = fmaxf(m1r, mc1);
        const float sc0 = __expf(m0r - mn0), sc1 = __expf(m1r - mn1);
        m0r = mn0; m1r = mn1;

        float rs0 = 0.0f, rs1 = 0.0f;
        #pragma unroll
        for (int nt = 0; nt < 16; nt++) {
            float p0 = __expf(0.125f * sacc[nt][0] - mn0);
            float p1 = __expf(0.125f * sacc[nt][1] - mn0);
            float p2 = __expf(0.125f * sacc[nt][2] - mn1);
            float p3 = __expf(0.125f * sacc[nt][3] - mn1);
            sacc[nt][0] = p0; sacc[nt][1] = p1; sacc[nt][2] = p2; sacc[nt][3] = p3;
            rs0 += p0 + p1; rs1 += p2 + p3;
        }
        rs0 += __shfl_xor_sync(0xffffffffu, rs0, 1);
        rs0 += __shfl_xor_sync(0xffffffffu, rs0, 2);
        rs1 += __shfl_xor_sync(0xffffffffu, rs1, 1);
        rs1 += __shfl_xor_sync(0xffffffffu, rs1, 2);
        sum0 = sum0 * sc0 + rs0;
        sum1 = sum1 * sc1 + rs1;
        #pragma unroll
        for (int nt = 0; nt < 8; nt++) {
            avacc[nt][0] *= sc0; avacc[nt][1] *= sc0;
            avacc[nt][2] *= sc1; avacc[nt][3] *= sc1;
        }

        #pragma unroll
        for (int kt = 0; kt < 8; kt++) {
            bf16 hh[8], ll[8];
            bfsplit(sacc[2*kt][0],   hh[0], ll[0]);
            bfsplit(sacc[2*kt][1],   hh[1], ll[1]);
            bfsplit(sacc[2*kt][2],   hh[2], ll[2]);
            bfsplit(sacc[2*kt][3],   hh[3], ll[3]);
            bfsplit(sacc[2*kt+1][0], hh[4], ll[4]);
            bfsplit(sacc[2*kt+1][1], hh[5], ll[5]);
            bfsplit(sacc[2*kt+1][2], hh[6], ll[6]);
            bfsplit(sacc[2*kt+1][3], hh[7], ll[7]);
            unsigned ah[4] = {pack2(hh[0],hh[1]), pack2(hh[2],hh[3]),
                              pack2(hh[4],hh[5]), pack2(hh[6],hh[7])};
            unsigned al[4] = {pack2(ll[0],ll[1]), pack2(ll[2],ll[3]),
                              pack2(ll[4],ll[5]), pack2(ll[6],ll[7])};
            #pragma unroll
            for (int p = 0; p < 4; p++) {
                int rB = p * 16 + bLR;
                unsigned boff = (unsigned)rB * 256 + ((unsigned)((2*kt + bLC) ^ (rB & 7))) * 16;
                unsigned vh[4], vl[4];
                ldsm4(vh[0], vh[1], vh[2], vh[3], sb + VH + boff);
                ldsm4(vl[0], vl[1], vl[2], vl[3], sb + VL + boff);
                mma_bf16(avacc[2*p],   ah, &vh[0]);
                mma_bf16(avacc[2*p],   ah, &vl[0]);
                mma_bf16(avacc[2*p],   al, &vh[0]);
                mma_bf16(avacc[2*p+1], ah, &vh[2]);
                mma_bf16(avacc[2*p+1], ah, &vl[2]);
                mma_bf16(avacc[2*p+1], al, &vh[2]);
            }
        }
        __syncthreads();
    }

    const float i0 = 1.0f / sum0, i1 = 1.0f / sum1;
    float* Xs = (float*)(smraw + 32768);
    #pragma unroll
    for (int nt = 0; nt < 8; nt++) {
        const int col = 8 * nt + 2 * tig;
        Xs[(m_w + gid)     * 64 + col]     = avacc[nt][0] * i0;
        Xs[(m_w + gid)     * 64 + col + 1] = avacc[nt][1] * i0;
        Xs[(m_w + gid + 8) * 64 + col]     = avacc[nt][2] * i1;
        Xs[(m_w + gid + 8) * 64 + col + 1] = avacc[nt][3] * i1;
    }
    __syncthreads();

    #pragma unroll
    for (int r = 0; r < 8; r++) {
        int i = (t + r * 256) * 4;
        int row = i >> 6, d0 = i & 63;
        float4 v = *(const float4*)&Xs[row * 64 + d0];
        bf16 h0,l0,h1,l1,h2,l2,h3,l3;
        bfsplit(v.x,h0,l0); bfsplit(v.y,h1,l1); bfsplit(v.z,h2,l2); bfsplit(v.w,h3,l3);
        size_t ad = ((size_t)(b * Sv + q0 + row)) * Dv + h * HDv + d0;
        *(uint2*)&g_XoHi[ad] = make_uint2(pack2(h0,h1), pack2(h2,h3));
        *(uint2*)&g_XoLo[ad] = make_uint2(pack2(l0,l1), pack2(l2,l3));
    }
}

// ============================================================================
extern "C" void kernel_launch(void* const* d_in, const int* in_sizes, int n_in,
                              void* d_out, int out_size)
{
    const float* X    = (const float*)d_in[0];
    const float* mask = (const float*)d_in[1];
    const float* Wq   = (const float*)d_in[2];
    const float* bq   = (const float*)d_in[3];
    const float* Wk   = (const float*)d_in[4];
    const float* bk   = (const float*)d_in[5];
    const float* Wv   = (const float*)d_in[6];
    const float* bv   = (const float*)d_in[7];
    const float* E    = (const float*)d_in[8];
    const float* Wo   = (const float*)d_in[9];
    const float* bo   = (const float*)d_in[10];
    float* out        = (float*)d_out;

    bf16 *xhi, *xlo, *ehi, *elo, *wth, *wtl, *xoh, *xol;
    cudaGetSymbolAddress((void**)&xhi, g_Xhi);  cudaGetSymbolAddress((void**)&xlo, g_Xlo);
    cudaGetSymbolAddress((void**)&ehi, g_Ehi);  cudaGetSymbolAddress((void**)&elo, g_Elo);
    cudaGetSymbolAddress((void**)&wth, g_Wt_hi);cudaGetSymbolAddress((void**)&wtl, g_Wt_lo);
    cudaGetSymbolAddress((void**)&xoh, g_XoHi); cudaGetSymbolAddress((void**)&xol, g_XoLo);

    const long long WSZ = (long long)Dv * Dv;

    const int SMEM_G = 3 * 32768;   // main GEMM core: 3 stages x 32KB
    const int SMEM_P = 3 * 24576;   // proj core:      3 stages x 24KB
    cudaFuncSetAttribute(gemm_qkv, cudaFuncAttributeMaxDynamicSharedMemorySize, SMEM_G);
    cudaFuncSetAttribute(gemm_out, cudaFuncAttributeMaxDynamicSharedMemorySize, SMEM_G);
    cudaFuncSetAttribute(proj_tc,  cudaFuncAttributeMaxDynamicSharedMemorySize, SMEM_P);
    cudaFuncSetAttribute(attn_mma, cudaFuncAttributeMaxDynamicSharedMemorySize, ATTN_SMEM);

    // -------- prepass --------
    split_k<<<(int)(NELEM/4/256), 256>>>(X, xhi, xlo, (int)(NELEM/4));
    split_k<<<(int)(NELEM/4/256), 256>>>(E, ehi, elo, (int)(NELEM/4));
    tsplit_k<<<dim3(32,32), dim3(32,8)>>>(Wq, wth + 0*WSZ, wtl + 0*WSZ);
    tsplit_k<<<dim3(32,32), dim3(32,8)>>>(Wk, wth + 1*WSZ, wtl + 1*WSZ);
    tsplit_k<<<dim3(32,32), dim3(32,8)>>>(Wv, wth + 2*WSZ, wtl + 2*WSZ);
    tsplit_k<<<dim3(32,32), dim3(32,8)>>>(Wo, wth + 3*WSZ, wtl + 3*WSZ);
    pack_bias<<<12, 256>>>(bq, bk, bv);

    // -------- fused QKV (N=3072, one launch) --------
    gemm_qkv<<<dim3(3 * Dv / 128, Mrows / 128), 256, SMEM_G>>>(xhi, xlo, wth, wtl, mask);

    // -------- Kp / VpT --------
    proj_tc<<<dim3(LKv/128, Bv*Hv, 2), 256, SMEM_P>>>();

    // -------- tensorized attention -> XoHi/XoLo --------
    attn_mma<<<dim3(Sv/128, Bv*Hv), 256, ATTN_SMEM>>>();

    // -------- output projection -> d_out --------
    gemm_out<<<dim3(Dv/128, Mrows/128), 256, SMEM_G>>>(xoh, xol, wth + 3*WSZ, wtl + 3*WSZ,
                                                       bo, out);
}